// round 12
// baseline (speedup 1.0000x reference)
#include <cuda_runtime.h>
#include <cuda_fp16.h>
#include <cstdint>

// Problem constants: B=32, N=1024, C=128, L=4
#define BB 32
#define NN 1024
#define CC 128
#define LL 4
#define ROWS (BB * NN)          // 32768
#define HSZ  (ROWS * CC)
#define GSZ  (ROWS * 3 * CC)

// fp32 scratch
__device__ __align__(16) float g_gx[GSZ];
__device__ __align__(16) float g_gh[GSZ];
// fp16 scratch
__device__ __align__(16) __half g_adjT[(size_t)BB * NN * NN];   // [b][n][j] exact
__device__ __align__(16) __half g_hwT_hi[HSZ];                  // [d][b*N+j]
__device__ __align__(16) __half g_hwT_lo[HSZ];
__device__ __align__(16) __half g_hA_hi[HSZ];                   // h splits (ping)
__device__ __align__(16) __half g_hA_lo[HSZ];
__device__ __align__(16) __half g_hB_hi[HSZ];                   // h splits (pong)
__device__ __align__(16) __half g_hB_lo[HSZ];
__device__ __align__(16) __half g_mA_hi[HSZ];                   // m splits
__device__ __align__(16) __half g_mA_lo[HSZ];
__device__ __align__(16) __half g_wT_hi[LL * CC * CC];          // [l][d][c]
__device__ __align__(16) __half g_wT_lo[LL * CC * CC];
__device__ __align__(16) __half g_wih_hi[LL * 3 * CC * CC];
__device__ __align__(16) __half g_wih_lo[LL * 3 * CC * CC];
__device__ __align__(16) __half g_whh_hi[LL * 3 * CC * CC];
__device__ __align__(16) __half g_whh_lo[LL * 3 * CC * CC];

// ===========================================================================
// helpers
// ===========================================================================
__device__ __forceinline__ uint32_t smem_u32(const void* p) {
    uint32_t a;
    asm("{ .reg .u64 t; cvta.to.shared.u64 t, %1; cvt.u32.u64 %0, t; }"
        : "=r"(a) : "l"(p));
    return a;
}
__device__ __forceinline__ void cp16(uint32_t s, const void* g) {
    asm volatile("cp.async.cg.shared.global [%0], [%1], 16;" :: "r"(s), "l"(g));
}
#define CP_COMMIT() asm volatile("cp.async.commit_group;" ::: "memory")
#define CP_WAIT(n)  asm volatile("cp.async.wait_group %0;" :: "n"(n) : "memory")

#define LDSM4(R0, R1, R2, R3, ADDR)                                          \
    asm volatile("ldmatrix.sync.aligned.m8n8.x4.shared.b16 {%0,%1,%2,%3}, [%4];" \
                 : "=r"(R0), "=r"(R1), "=r"(R2), "=r"(R3) : "r"(ADDR))

#define MMA16816(D, A, B0, B1)                                               \
    asm volatile(                                                            \
        "mma.sync.aligned.m16n8k16.row.col.f32.f16.f16.f32 "                 \
        "{%0,%1,%2,%3},{%4,%5,%6,%7},{%8,%9},{%0,%1,%2,%3};"                 \
        : "+f"((D)[0]), "+f"((D)[1]), "+f"((D)[2]), "+f"((D)[3])             \
        : "r"((A)[0]), "r"((A)[1]), "r"((A)[2]), "r"((A)[3]),                \
          "r"(B0), "r"(B1))

// Load an R-row x 64-col fp16 tile (128B rows, XOR-16B swizzle) via cp.async.
template <int R>
__device__ __forceinline__ void cp_tile(const __half* __restrict__ g,
                                        int stride, uint32_t sdst, int t, int kc)
{
    #pragma unroll
    for (int u = 0; u < R / 32; ++u) {
        const int unit = t + u * 256;
        const int row  = unit >> 3;
        const int c16  = unit & 7;
        const uint32_t sw = ((row << 7) + (c16 << 4)) ^ ((row & 7) << 4);
        cp16(sdst + sw, g + (size_t)row * stride + (kc << 6) + (c16 << 3));
    }
}

// ===========================================================================
// fused adj + gh kernel (R11 verbatim).
// CTAs [0,128):   m[b][n][d] = adjT[b] @ (hw_hi+hw_lo)   (3-stage pipeline)
// CTAs [128,512): gh = h @ w_hh^T + b_hh                 (2-stage, 3-product)
// ===========================================================================
__global__ __launch_bounds__(256)
void fused_adj_gh(const __half* __restrict__ adjT,
                  const __half* __restrict__ hwhi, const __half* __restrict__ hwlo,
                  __half* __restrict__ mhi, __half* __restrict__ mlo,
                  const __half* __restrict__ hhi, const __half* __restrict__ hlo,
                  const __half* __restrict__ whh_hi, const __half* __restrict__ whh_lo,
                  float* __restrict__ gh, const float* __restrict__ bias_hh)
{
    extern __shared__ __align__(128) char smem[];
    const uint32_t sbase = smem_u32(smem);

    const int t     = threadIdx.x;
    const int lane  = t & 31;
    const int warp  = t >> 5;
    const int mwarp = (warp >> 1) * 64;
    const int nwarp = (warp & 1) * 64;

    if (blockIdx.x < 128) {
        constexpr uint32_t ATSZ = 32768;
        constexpr uint32_t BTSZ = 16384;
        constexpr uint32_t STG  = ATSZ + 2 * BTSZ;

        const int mtile = blockIdx.x & 3;
        const int z     = blockIdx.x >> 2;
        const int m0    = mtile * 256;

        const __half* Ag = adjT + (size_t)z * NN * NN + (size_t)m0 * NN;
        const __half* Bh = hwhi + (size_t)z * NN;
        const __half* Bl = hwlo + (size_t)z * NN;

        constexpr int NC = NN >> 6;

        float acc[4][8][4];
        #pragma unroll
        for (int i = 0; i < 4; i++)
            #pragma unroll
            for (int j = 0; j < 8; j++)
                #pragma unroll
                for (int q = 0; q < 4; q++)
                    acc[i][j][q] = 0.0f;

        auto load_stage = [&](int kc, uint32_t sb) {
            cp_tile<256>(Ag, NN, sb, t, kc);
            cp_tile<128>(Bh, ROWS, sb + ATSZ, t, kc);
            cp_tile<128>(Bl, ROWS, sb + ATSZ + BTSZ, t, kc);
            CP_COMMIT();
        };

        load_stage(0, sbase);
        load_stage(1, sbase + STG);

        for (int c = 0; c < NC; ++c) {
            const int nxt = c + 2;
            if (nxt < NC) load_stage(nxt, sbase + (nxt % 3) * STG);
            const int nleft = NC - 1 - c;
            if (nleft >= 2)      CP_WAIT(2);
            else if (nleft == 1) CP_WAIT(1);
            else                 CP_WAIT(0);
            __syncthreads();

            const uint32_t S = sbase + (c % 3) * STG;
            const uint32_t Bb = S + ATSZ;

            #pragma unroll
            for (int ks = 0; ks < 4; ++ks) {
                uint32_t ah[4][4];
                #pragma unroll
                for (int mb = 0; mb < 4; ++mb) {
                    const int row = mwarp + mb * 16 + (lane & 15);
                    const int col = ks * 32 + ((lane >> 4) << 4);
                    const uint32_t sw = (row << 7) + (col ^ ((row & 7) << 4));
                    LDSM4(ah[mb][0], ah[mb][1], ah[mb][2], ah[mb][3], S + sw);
                }
                uint32_t bh[4][4], bl[4][4];
                #pragma unroll
                for (int nq = 0; nq < 4; ++nq) {
                    const int row = nwarp + nq * 16 + ((lane >> 4) << 3) + (lane & 7);
                    const int col = ks * 32 + (((lane >> 3) & 1) << 4);
                    const uint32_t sw = (row << 7) + (col ^ ((row & 7) << 4));
                    LDSM4(bh[nq][0], bh[nq][1], bh[nq][2], bh[nq][3], Bb + sw);
                    LDSM4(bl[nq][0], bl[nq][1], bl[nq][2], bl[nq][3], Bb + BTSZ + sw);
                }
                #pragma unroll
                for (int mb = 0; mb < 4; ++mb)
                    #pragma unroll
                    for (int n = 0; n < 8; ++n) {
                        const int q0 = (n & 1) * 2;
                        MMA16816(acc[mb][n], ah[mb], bh[n >> 1][q0], bh[n >> 1][q0 + 1]);
                        MMA16816(acc[mb][n], ah[mb], bl[n >> 1][q0], bl[n >> 1][q0 + 1]);
                    }
            }
            __syncthreads();
        }

        const int rbase = m0 + mwarp + (lane >> 2);
        const int cbase = nwarp + (lane & 3) * 2;
        __half* CH = mhi + (size_t)z * NN * CC;
        __half* CL = mlo + (size_t)z * NN * CC;
        #pragma unroll
        for (int mb = 0; mb < 4; ++mb) {
            #pragma unroll
            for (int n = 0; n < 8; ++n) {
                const int gc = cbase + n * 8;
                const int r  = rbase + mb * 16;
                #pragma unroll
                for (int hf = 0; hf < 2; ++hf) {
                    const float v0 = acc[mb][n][hf * 2 + 0];
                    const float v1 = acc[mb][n][hf * 2 + 1];
                    const __half h0 = __float2half_rn(v0);
                    const __half h1 = __float2half_rn(v1);
                    __half2 ph; ph.x = h0; ph.y = h1;
                    __half2 pl;
                    pl.x = __float2half_rn(v0 - __half2float(h0));
                    pl.y = __float2half_rn(v1 - __half2float(h1));
                    const size_t off = (size_t)(r + hf * 8) * CC + gc;
                    *reinterpret_cast<__half2*>(&CH[off]) = ph;
                    *reinterpret_cast<__half2*>(&CL[off]) = pl;
                }
            }
        }
    } else {
        constexpr uint32_t ATSZ = 32768;
        constexpr uint32_t BTSZ = 16384;
        constexpr uint32_t STG  = 2 * ATSZ + 2 * BTSZ;

        const int id = blockIdx.x - 128;
        const int n0 = (id % 3) * 128;
        const int m0 = (id / 3) * 256;

        const __half* Ah = hhi + (size_t)m0 * CC;
        const __half* Al = hlo + (size_t)m0 * CC;
        const __half* Bh = whh_hi + (size_t)n0 * CC;
        const __half* Bl = whh_lo + (size_t)n0 * CC;

        constexpr int NC = 2;

        float acc[4][8][4];
        #pragma unroll
        for (int i = 0; i < 4; i++)
            #pragma unroll
            for (int j = 0; j < 8; j++)
                #pragma unroll
                for (int q = 0; q < 4; q++)
                    acc[i][j][q] = 0.0f;

        auto load_stage = [&](int kc, uint32_t sb) {
            cp_tile<256>(Ah, CC, sb, t, kc);
            cp_tile<256>(Al, CC, sb + ATSZ, t, kc);
            cp_tile<128>(Bh, CC, sb + 2 * ATSZ, t, kc);
            cp_tile<128>(Bl, CC, sb + 2 * ATSZ + BTSZ, t, kc);
            CP_COMMIT();
        };

        load_stage(0, sbase);
        load_stage(1, sbase + STG);

        #pragma unroll
        for (int c = 0; c < NC; ++c) {
            if (c == 0) CP_WAIT(1); else CP_WAIT(0);
            __syncthreads();

            const uint32_t S = sbase + c * STG;
            const uint32_t Bb = S + 2 * ATSZ;

            #pragma unroll
            for (int ks = 0; ks < 4; ++ks) {
                uint32_t ah[4][4], al[4][4];
                #pragma unroll
                for (int mb = 0; mb < 4; ++mb) {
                    const int row = mwarp + mb * 16 + (lane & 15);
                    const int col = ks * 32 + ((lane >> 4) << 4);
                    const uint32_t sw = (row << 7) + (col ^ ((row & 7) << 4));
                    LDSM4(ah[mb][0], ah[mb][1], ah[mb][2], ah[mb][3], S + sw);
                    LDSM4(al[mb][0], al[mb][1], al[mb][2], al[mb][3], S + ATSZ + sw);
                }
                uint32_t bh[4][4], bl[4][4];
                #pragma unroll
                for (int nq = 0; nq < 4; ++nq) {
                    const int row = nwarp + nq * 16 + ((lane >> 4) << 3) + (lane & 7);
                    const int col = ks * 32 + (((lane >> 3) & 1) << 4);
                    const uint32_t sw = (row << 7) + (col ^ ((row & 7) << 4));
                    LDSM4(bh[nq][0], bh[nq][1], bh[nq][2], bh[nq][3], Bb + sw);
                    LDSM4(bl[nq][0], bl[nq][1], bl[nq][2], bl[nq][3], Bb + BTSZ + sw);
                }
                #pragma unroll
                for (int mb = 0; mb < 4; ++mb)
                    #pragma unroll
                    for (int n = 0; n < 8; ++n) {
                        const int q0 = (n & 1) * 2;
                        MMA16816(acc[mb][n], ah[mb], bh[n >> 1][q0], bh[n >> 1][q0 + 1]);
                        MMA16816(acc[mb][n], ah[mb], bl[n >> 1][q0], bl[n >> 1][q0 + 1]);
                        MMA16816(acc[mb][n], al[mb], bh[n >> 1][q0], bh[n >> 1][q0 + 1]);
                    }
            }
            __syncthreads();
        }

        const int rbase = m0 + mwarp + (lane >> 2);
        const int cbase = n0 + nwarp + (lane & 3) * 2;
        #pragma unroll
        for (int mb = 0; mb < 4; ++mb) {
            #pragma unroll
            for (int n = 0; n < 8; ++n) {
                const int gc = cbase + n * 8;
                const float bx = bias_hh[gc];
                const float by = bias_hh[gc + 1];
                const int r = rbase + mb * 16;
                float2 v0 = { acc[mb][n][0] + bx, acc[mb][n][1] + by };
                float2 v1 = { acc[mb][n][2] + bx, acc[mb][n][3] + by };
                *reinterpret_cast<float2*>(&gh[(size_t)r * (3 * CC) + gc])       = v0;
                *reinterpret_cast<float2*>(&gh[(size_t)(r + 8) * (3 * CC) + gc]) = v1;
            }
        }
    }
}

// ===========================================================================
// gate_mma: gx = m @ w_ih^T + b_ih  (3-product, fp32 out, ldc=384)
// ===========================================================================
__global__ __launch_bounds__(256)
void gate_mma(const __half* __restrict__ a_hi, const __half* __restrict__ a_lo,
              const __half* __restrict__ b_hi, const __half* __restrict__ b_lo,
              float* __restrict__ C, const float* __restrict__ bias)
{
    constexpr uint32_t ATSZ = 32768;
    constexpr uint32_t BTSZ = 16384;
    constexpr uint32_t STG  = 2 * ATSZ + 2 * BTSZ;
    extern __shared__ __align__(128) char smem[];
    const uint32_t sbase = smem_u32(smem);

    const int t     = threadIdx.x;
    const int lane  = t & 31;
    const int warp  = t >> 5;
    const int mwarp = (warp >> 1) * 64;
    const int nwarp = (warp & 1) * 64;
    const int m0 = blockIdx.y * 256;
    const int n0 = blockIdx.x * 128;

    const __half* Ah = a_hi + (size_t)m0 * CC;
    const __half* Al = a_lo + (size_t)m0 * CC;
    const __half* Bh = b_hi + (size_t)n0 * CC;
    const __half* Bl = b_lo + (size_t)n0 * CC;

    constexpr int NC = 2;

    float acc[4][8][4];
    #pragma unroll
    for (int i = 0; i < 4; i++)
        #pragma unroll
        for (int j = 0; j < 8; j++)
            #pragma unroll
            for (int q = 0; q < 4; q++)
                acc[i][j][q] = 0.0f;

    auto load_stage = [&](int kc, uint32_t sb) {
        cp_tile<256>(Ah, CC, sb, t, kc);
        cp_tile<256>(Al, CC, sb + ATSZ, t, kc);
        cp_tile<128>(Bh, CC, sb + 2 * ATSZ, t, kc);
        cp_tile<128>(Bl, CC, sb + 2 * ATSZ + BTSZ, t, kc);
        CP_COMMIT();
    };

    load_stage(0, sbase);
    load_stage(1, sbase + STG);

    #pragma unroll
    for (int c = 0; c < NC; ++c) {
        if (c == 0) CP_WAIT(1); else CP_WAIT(0);
        __syncthreads();

        const uint32_t S = sbase + c * STG;
        const uint32_t Bb = S + 2 * ATSZ;

        #pragma unroll
        for (int ks = 0; ks < 4; ++ks) {
            uint32_t ah[4][4], al[4][4];
            #pragma unroll
            for (int mb = 0; mb < 4; ++mb) {
                const int row = mwarp + mb * 16 + (lane & 15);
                const int col = ks * 32 + ((lane >> 4) << 4);
                const uint32_t sw = (row << 7) + (col ^ ((row & 7) << 4));
                LDSM4(ah[mb][0], ah[mb][1], ah[mb][2], ah[mb][3], S + sw);
                LDSM4(al[mb][0], al[mb][1], al[mb][2], al[mb][3], S + ATSZ + sw);
            }
            uint32_t bh[4][4], bl[4][4];
            #pragma unroll
            for (int nq = 0; nq < 4; ++nq) {
                const int row = nwarp + nq * 16 + ((lane >> 4) << 3) + (lane & 7);
                const int col = ks * 32 + (((lane >> 3) & 1) << 4);
                const uint32_t sw = (row << 7) + (col ^ ((row & 7) << 4));
                LDSM4(bh[nq][0], bh[nq][1], bh[nq][2], bh[nq][3], Bb + sw);
                LDSM4(bl[nq][0], bl[nq][1], bl[nq][2], bl[nq][3], Bb + BTSZ + sw);
            }
            #pragma unroll
            for (int mb = 0; mb < 4; ++mb)
                #pragma unroll
                for (int n = 0; n < 8; ++n) {
                    const int q0 = (n & 1) * 2;
                    MMA16816(acc[mb][n], ah[mb], bh[n >> 1][q0], bh[n >> 1][q0 + 1]);
                    MMA16816(acc[mb][n], ah[mb], bl[n >> 1][q0], bl[n >> 1][q0 + 1]);
                    MMA16816(acc[mb][n], al[mb], bh[n >> 1][q0], bh[n >> 1][q0 + 1]);
                }
        }
        __syncthreads();
    }

    const int rbase = m0 + mwarp + (lane >> 2);
    const int cbase = n0 + nwarp + (lane & 3) * 2;
    #pragma unroll
    for (int mb = 0; mb < 4; ++mb) {
        #pragma unroll
        for (int n = 0; n < 8; ++n) {
            const int gc = cbase + n * 8;
            const float bx = bias[gc];
            const float by = bias[gc + 1];
            const int r = rbase + mb * 16;
            float2 v0 = { acc[mb][n][0] + bx, acc[mb][n][1] + by };
            float2 v1 = { acc[mb][n][2] + bx, acc[mb][n][3] + by };
            *reinterpret_cast<float2*>(&C[(size_t)r * (3 * CC) + gc])       = v0;
            *reinterpret_cast<float2*>(&C[(size_t)(r + 8) * (3 * CC) + gc]) = v1;
        }
    }
}

// ===========================================================================
// wmma2_hw (128x128 CTA): 3-product fp16 split GEMM for hw — layer 0 only.
// ===========================================================================
__global__ __launch_bounds__(256)
void wmma2_hw(const __half* __restrict__ a_hi, const __half* __restrict__ a_lo,
              const __half* __restrict__ b_hi, const __half* __restrict__ b_lo,
              __half* __restrict__ Chi, __half* __restrict__ Clo,
              int K, int lda, int ldb, int ldc)
{
    constexpr uint32_t TSZ = 16384;
    constexpr uint32_t STG = 4 * TSZ;
    extern __shared__ __align__(128) char smem[];
    const uint32_t sbase = smem_u32(smem);

    const int t     = threadIdx.x;
    const int lane  = t & 31;
    const int warp  = t >> 5;
    const int mwarp = (warp >> 1) * 32;
    const int nwarp = (warp & 1) * 64;
    const int m0 = blockIdx.y * 128;
    const int n0 = blockIdx.x * 128;

    const __half* Ah = a_hi + (size_t)m0 * lda;
    const __half* Al = a_lo + (size_t)m0 * lda;
    const __half* Bh = b_hi + (size_t)n0 * ldb;
    const __half* Bl = b_lo + (size_t)n0 * ldb;

    const int NC = K >> 6;

    float acc[2][8][4];
    #pragma unroll
    for (int i = 0; i < 2; i++)
        #pragma unroll
        for (int j = 0; j < 8; j++)
            #pragma unroll
            for (int q = 0; q < 4; q++)
                acc[i][j][q] = 0.0f;

    auto load_stage = [&](int kc, uint32_t sb) {
        cp_tile<128>(Ah, lda, sb, t, kc);
        cp_tile<128>(Al, lda, sb + TSZ, t, kc);
        cp_tile<128>(Bh, ldb, sb + 2 * TSZ, t, kc);
        cp_tile<128>(Bl, ldb, sb + 3 * TSZ, t, kc);
        CP_COMMIT();
    };

    load_stage(0, sbase);

    for (int c = 0; c < NC; ++c) {
        const int buf = c & 1;
        if (c + 1 < NC) {
            load_stage(c + 1, sbase + ((c + 1) & 1) * STG);
            CP_WAIT(1);
        } else {
            CP_WAIT(0);
        }
        __syncthreads();

        const uint32_t S = sbase + buf * STG;

        #pragma unroll
        for (int ks = 0; ks < 4; ++ks) {
            uint32_t ah[2][4], al[2][4];
            #pragma unroll
            for (int mb = 0; mb < 2; ++mb) {
                const int row = mwarp + mb * 16 + (lane & 15);
                const int col = ks * 32 + ((lane >> 4) << 4);
                const uint32_t sw = (row << 7) + (col ^ ((row & 7) << 4));
                LDSM4(ah[mb][0], ah[mb][1], ah[mb][2], ah[mb][3], S + sw);
                LDSM4(al[mb][0], al[mb][1], al[mb][2], al[mb][3], S + TSZ + sw);
            }
            uint32_t bh[4][4], bl[4][4];
            #pragma unroll
            for (int nq = 0; nq < 4; ++nq) {
                const int row = nwarp + nq * 16 + ((lane >> 4) << 3) + (lane & 7);
                const int col = ks * 32 + (((lane >> 3) & 1) << 4);
                const uint32_t sw = (row << 7) + (col ^ ((row & 7) << 4));
                LDSM4(bh[nq][0], bh[nq][1], bh[nq][2], bh[nq][3], S + 2 * TSZ + sw);
                LDSM4(bl[nq][0], bl[nq][1], bl[nq][2], bl[nq][3], S + 3 * TSZ + sw);
            }
            #pragma unroll
            for (int mb = 0; mb < 2; ++mb)
                #pragma unroll
                for (int n = 0; n < 8; ++n) {
                    const int q0 = (n & 1) * 2;
                    MMA16816(acc[mb][n], ah[mb], bh[n >> 1][q0], bh[n >> 1][q0 + 1]);
                    MMA16816(acc[mb][n], ah[mb], bl[n >> 1][q0], bl[n >> 1][q0 + 1]);
                    MMA16816(acc[mb][n], al[mb], bh[n >> 1][q0], bh[n >> 1][q0 + 1]);
                }
        }
        __syncthreads();
    }

    const int rbase = m0 + mwarp + (lane >> 2);
    const int cbase = n0 + nwarp + (lane & 3) * 2;
    #pragma unroll
    for (int mb = 0; mb < 2; ++mb) {
        #pragma unroll
        for (int n = 0; n < 8; ++n) {
            const int gc = cbase + n * 8;
            const int r  = rbase + mb * 16;
            #pragma unroll
            for (int hf = 0; hf < 2; ++hf) {
                const float v0 = acc[mb][n][hf * 2 + 0];
                const float v1 = acc[mb][n][hf * 2 + 1];
                const __half h0 = __float2half_rn(v0);
                const __half h1 = __float2half_rn(v1);
                __half2 ph; ph.x = h0; ph.y = h1;
                __half2 pl;
                pl.x = __float2half_rn(v0 - __half2float(h0));
                pl.y = __float2half_rn(v1 - __half2float(h1));
                const size_t off = (size_t)(r + hf * 8) * ldc + gc;
                *reinterpret_cast<__half2*>(&Chi[off]) = ph;
                *reinterpret_cast<__half2*>(&Clo[off]) = pl;
            }
        }
    }
}

// ===========================================================================
// gru_hw: fused GRU elementwise + next-layer hw GEMM.
// CTA = 128 rows. Phase 1: GRU -> h splits (global + smem B tiles).
// Phase 2: hwT[d][r0+j] = sum_c WT[d][c]*h[j][c]  (3-product, A=WT prefetched).
// SMEM layout: [0,32K) Bhi (2 k-chunks), [32K,64K) Blo, [64K,96K) Ahi, [96K,128K) Alo.
// ===========================================================================
__global__ __launch_bounds__(256)
void gru_hw(const float* __restrict__ gx, const float* __restrict__ gh,
            const __half* __restrict__ hhi_in, const __half* __restrict__ hlo_in,
            __half* __restrict__ hhi_out, __half* __restrict__ hlo_out,
            const __half* __restrict__ WThi, const __half* __restrict__ WTlo,
            __half* __restrict__ hwhi, __half* __restrict__ hwlo,
            float* __restrict__ outF, const float* __restrict__ mask, int isLast)
{
    extern __shared__ __align__(128) char smem[];
    const uint32_t sbase = smem_u32(smem);
    const uint32_t Bhi_s = sbase;
    const uint32_t Blo_s = sbase + 32768;
    const uint32_t Ahi_s = sbase + 65536;
    const uint32_t Alo_s = sbase + 98304;

    const int t  = threadIdx.x;
    const int r0 = blockIdx.x * 128;

    // prefetch WT (next layer) under phase 1
    if (!isLast) {
        cp_tile<128>(WThi, CC, Ahi_s, t, 0);
        cp_tile<128>(WThi, CC, Ahi_s + 16384, t, 1);
        cp_tile<128>(WTlo, CC, Alo_s, t, 0);
        cp_tile<128>(WTlo, CC, Alo_s + 16384, t, 1);
        CP_COMMIT();
    }

    // ---- phase 1: GRU ----
    #pragma unroll 4
    for (int k = 0; k < 32; ++k) {
        const int u  = t + k * 256;        // 0..8191
        const int rl = u >> 6;             // 0..127
        const int c0 = (u & 63) * 2;       // even channel
        const int row = r0 + rl;
        const size_t idx = (size_t)row * CC + c0;
        const size_t gb  = (size_t)row * (3 * CC);

        const float2 xr = *reinterpret_cast<const float2*>(&gx[gb + c0]);
        const float2 xz = *reinterpret_cast<const float2*>(&gx[gb + CC + c0]);
        const float2 xn = *reinterpret_cast<const float2*>(&gx[gb + 2 * CC + c0]);
        const float2 hr = *reinterpret_cast<const float2*>(&gh[gb + c0]);
        const float2 hz = *reinterpret_cast<const float2*>(&gh[gb + CC + c0]);
        const float2 hn = *reinterpret_cast<const float2*>(&gh[gb + 2 * CC + c0]);
        const __half2 hh = *reinterpret_cast<const __half2*>(&hhi_in[idx]);
        const __half2 hl = *reinterpret_cast<const __half2*>(&hlo_in[idx]);
        const float h0 = __half2float(hh.x) + __half2float(hl.x);
        const float h1 = __half2float(hh.y) + __half2float(hl.y);

        const float rg0 = 1.0f / (1.0f + __expf(-(xr.x + hr.x)));
        const float rg1 = 1.0f / (1.0f + __expf(-(xr.y + hr.y)));
        const float zg0 = 1.0f / (1.0f + __expf(-(xz.x + hz.x)));
        const float zg1 = 1.0f / (1.0f + __expf(-(xz.y + hz.y)));
        const float ng0 = tanhf(xn.x + rg0 * hn.x);
        const float ng1 = tanhf(xn.y + rg1 * hn.y);
        const float hnew0 = (1.0f - zg0) * ng0 + zg0 * h0;
        const float hnew1 = (1.0f - zg1) * ng1 + zg1 * h1;

        if (isLast) {
            const float mk = mask[row];
            float2 o = { hnew0 * mk, hnew1 * mk };
            *reinterpret_cast<float2*>(&outF[idx]) = o;
        } else {
            const __half H0 = __float2half_rn(hnew0);
            const __half H1 = __float2half_rn(hnew1);
            __half2 ph; ph.x = H0; ph.y = H1;
            __half2 pl;
            pl.x = __float2half_rn(hnew0 - __half2float(H0));
            pl.y = __float2half_rn(hnew1 - __half2float(H1));
            *reinterpret_cast<__half2*>(&hhi_out[idx]) = ph;
            *reinterpret_cast<__half2*>(&hlo_out[idx]) = pl;
            // smem B tiles (std 128-row x 64-col layout, XOR-16B swizzle)
            const int chunk = c0 >> 6;                 // k-chunk
            const int cb    = (c0 & 63) * 2;           // byte col in 128B row
            const uint32_t sw = (uint32_t)(rl << 7) +
                                (((uint32_t)(cb & 0x70)) ^ ((uint32_t)(rl & 7) << 4)) +
                                (uint32_t)(cb & 15);
            *reinterpret_cast<__half2*>(smem + chunk * 16384 + sw)         = ph;
            *reinterpret_cast<__half2*>(smem + 32768 + chunk * 16384 + sw) = pl;
        }
    }

    if (isLast) return;

    CP_WAIT(0);
    __syncthreads();

    // ---- phase 2: hwT GEMM (128x128x128, 3-product) ----
    const int lane  = t & 31;
    const int warp  = t >> 5;
    const int mwarp = (warp >> 1) * 32;    // d
    const int nwarp = (warp & 1) * 64;     // j

    float acc[2][8][4];
    #pragma unroll
    for (int i = 0; i < 2; i++)
        #pragma unroll
        for (int j = 0; j < 8; j++)
            #pragma unroll
            for (int q = 0; q < 4; q++)
                acc[i][j][q] = 0.0f;

    #pragma unroll
    for (int kc = 0; kc < 2; ++kc) {
        const uint32_t Sa_hi = Ahi_s + kc * 16384;
        const uint32_t Sa_lo = Alo_s + kc * 16384;
        const uint32_t Sb_hi = Bhi_s + kc * 16384;
        const uint32_t Sb_lo = Blo_s + kc * 16384;

        #pragma unroll
        for (int ks = 0; ks < 4; ++ks) {
            uint32_t ah[2][4], al[2][4];
            #pragma unroll
            for (int mb = 0; mb < 2; ++mb) {
                const int row = mwarp + mb * 16 + (lane & 15);
                const int col = ks * 32 + ((lane >> 4) << 4);
                const uint32_t sw = (row << 7) + (col ^ ((row & 7) << 4));
                LDSM4(ah[mb][0], ah[mb][1], ah[mb][2], ah[mb][3], Sa_hi + sw);
                LDSM4(al[mb][0], al[mb][1], al[mb][2], al[mb][3], Sa_lo + sw);
            }
            uint32_t bh[4][4], bl[4][4];
            #pragma unroll
            for (int nq = 0; nq < 4; ++nq) {
                const int row = nwarp + nq * 16 + ((lane >> 4) << 3) + (lane & 7);
                const int col = ks * 32 + (((lane >> 3) & 1) << 4);
                const uint32_t sw = (row << 7) + (col ^ ((row & 7) << 4));
                LDSM4(bh[nq][0], bh[nq][1], bh[nq][2], bh[nq][3], Sb_hi + sw);
                LDSM4(bl[nq][0], bl[nq][1], bl[nq][2], bl[nq][3], Sb_lo + sw);
            }
            #pragma unroll
            for (int mb = 0; mb < 2; ++mb)
                #pragma unroll
                for (int n = 0; n < 8; ++n) {
                    const int q0 = (n & 1) * 2;
                    MMA16816(acc[mb][n], ah[mb], bh[n >> 1][q0], bh[n >> 1][q0 + 1]);
                    MMA16816(acc[mb][n], ah[mb], bl[n >> 1][q0], bl[n >> 1][q0 + 1]);
                    MMA16816(acc[mb][n], al[mb], bh[n >> 1][q0], bh[n >> 1][q0 + 1]);
                }
        }
    }

    // epilogue: hwT[d][r0 + j], ldc = ROWS
    const int rbase = mwarp + (lane >> 2);          // d
    const int cbase = r0 + nwarp + (lane & 3) * 2;  // j (global row)
    #pragma unroll
    for (int mb = 0; mb < 2; ++mb) {
        #pragma unroll
        for (int n = 0; n < 8; ++n) {
            const int gc = cbase + n * 8;
            const int r  = rbase + mb * 16;
            #pragma unroll
            for (int hf = 0; hf < 2; ++hf) {
                const float v0 = acc[mb][n][hf * 2 + 0];
                const float v1 = acc[mb][n][hf * 2 + 1];
                const __half h0 = __float2half_rn(v0);
                const __half h1 = __float2half_rn(v1);
                __half2 ph; ph.x = h0; ph.y = h1;
                __half2 pl;
                pl.x = __float2half_rn(v0 - __half2float(h0));
                pl.y = __float2half_rn(v1 - __half2float(h1));
                const size_t off = (size_t)(r + hf * 8) * ROWS + gc;
                *reinterpret_cast<__half2*>(&hwhi[off]) = ph;
                *reinterpret_cast<__half2*>(&hwlo[off]) = pl;
            }
        }
    }
}

// ===========================================================================
// Prep kernels
// ===========================================================================
__global__ __launch_bounds__(256)
void adj_transpose(const float* __restrict__ adj, __half* __restrict__ adjT)
{
    __shared__ float tile[32][33];
    const int b  = blockIdx.z;
    const int j0 = blockIdx.x * 32;
    const int n0 = blockIdx.y * 32;
    const float* src = adj + (size_t)b * NN * NN;
    __half* dst = adjT + (size_t)b * NN * NN;
    const int tx = threadIdx.x & 31, ty = threadIdx.x >> 5;
    #pragma unroll
    for (int r = ty; r < 32; r += 8)
        tile[r][tx] = src[(size_t)(j0 + r) * NN + n0 + tx];
    __syncthreads();
    #pragma unroll
    for (int r = ty; r < 32; r += 8)
        dst[(size_t)(n0 + r) * NN + j0 + tx] = __float2half_rn(tile[tx][r]);
}

__global__ __launch_bounds__(256)
void split2(const float* __restrict__ x,
            __half* __restrict__ hi, __half* __restrict__ lo)
{
    const int i = blockIdx.x * blockDim.x + threadIdx.x;
    const float v = x[i];
    const __half h = __float2half_rn(v);
    hi[i] = h;
    lo[i] = __float2half_rn(v - __half2float(h));
}

// weight[l] fp32 [C][C] (W[c][d]) -> WT hi/lo fp16 [l][d][c]
__global__ __launch_bounds__(256)
void wT_split(const float* __restrict__ W,
              __half* __restrict__ hi, __half* __restrict__ lo)
{
    __shared__ float tile[32][33];
    const int l  = blockIdx.z;
    const int c0 = blockIdx.x * 32;
    const int d0 = blockIdx.y * 32;
    const float* src = W + (size_t)l * CC * CC;
    const size_t ob = (size_t)l * CC * CC;
    const int tx = threadIdx.x & 31, ty = threadIdx.x >> 5;
    #pragma unroll
    for (int r = ty; r < 32; r += 8)
        tile[r][tx] = src[(size_t)(c0 + r) * CC + d0 + tx];
    __syncthreads();
    #pragma unroll
    for (int r = ty; r < 32; r += 8) {
        const float v = tile[tx][r];
        const __half h = __float2half_rn(v);
        hi[ob + (size_t)(d0 + r) * CC + c0 + tx] = h;
        lo[ob + (size_t)(d0 + r) * CC + c0 + tx] = __float2half_rn(v - __half2float(h));
    }
}

// ===========================================================================
#define SMEM_BIG   (3 * (32768 + 2 * 16384))         // 192 KB
#define SMEM_HW    (2 * 4 * 16384)                   // 128 KB
#define SMEM_GRU   (128 * 1024)                      // 128 KB

extern "C" void kernel_launch(void* const* d_in, const int* in_sizes, int n_in,
                              void* d_out, int out_size)
{
    const float* x      = (const float*)d_in[0];
    const float* adj    = (const float*)d_in[1];
    const float* mask   = (const float*)d_in[2];
    const float* weight = (const float*)d_in[3];
    const float* w_ih   = (const float*)d_in[4];
    const float* w_hh   = (const float*)d_in[5];
    const float* b_ih   = (const float*)d_in[6];
    const float* b_hh   = (const float*)d_in[7];
    float* out = (float*)d_out;

    float *p_gx, *p_gh;
    __half *p_adjT, *p_hwhi, *p_hwlo, *p_mhi, *p_mlo;
    __half *p_hAhi, *p_hAlo, *p_hBhi, *p_hBlo;
    __half *p_wThi, *p_wTlo, *p_wihhi, *p_wihlo, *p_whhhi, *p_whhlo;
    cudaGetSymbolAddress((void**)&p_gx, g_gx);
    cudaGetSymbolAddress((void**)&p_gh, g_gh);
    cudaGetSymbolAddress((void**)&p_adjT, g_adjT);
    cudaGetSymbolAddress((void**)&p_hwhi, g_hwT_hi);
    cudaGetSymbolAddress((void**)&p_hwlo, g_hwT_lo);
    cudaGetSymbolAddress((void**)&p_mhi, g_mA_hi);
    cudaGetSymbolAddress((void**)&p_mlo, g_mA_lo);
    cudaGetSymbolAddress((void**)&p_hAhi, g_hA_hi);
    cudaGetSymbolAddress((void**)&p_hAlo, g_hA_lo);
    cudaGetSymbolAddress((void**)&p_hBhi, g_hB_hi);
    cudaGetSymbolAddress((void**)&p_hBlo, g_hB_lo);
    cudaGetSymbolAddress((void**)&p_wThi, g_wT_hi);
    cudaGetSymbolAddress((void**)&p_wTlo, g_wT_lo);
    cudaGetSymbolAddress((void**)&p_wihhi, g_wih_hi);
    cudaGetSymbolAddress((void**)&p_wihlo, g_wih_lo);
    cudaGetSymbolAddress((void**)&p_whhhi, g_whh_hi);
    cudaGetSymbolAddress((void**)&p_whhlo, g_whh_lo);

    cudaFuncSetAttribute(fused_adj_gh, cudaFuncAttributeMaxDynamicSharedMemorySize, SMEM_BIG);
    cudaFuncSetAttribute(gate_mma,     cudaFuncAttributeMaxDynamicSharedMemorySize, SMEM_BIG);
    cudaFuncSetAttribute(wmma2_hw,     cudaFuncAttributeMaxDynamicSharedMemorySize, SMEM_HW);
    cudaFuncSetAttribute(gru_hw,       cudaFuncAttributeMaxDynamicSharedMemorySize, SMEM_GRU);

    // ---- once per call ----
    adj_transpose<<<dim3(NN / 32, NN / 32, BB), 256>>>(adj, p_adjT);
    wT_split<<<dim3(CC / 32, CC / 32, LL), 256>>>(weight, p_wThi, p_wTlo);
    split2<<<(LL * 3 * CC * CC) / 256, 256>>>(w_ih, p_wihhi, p_wihlo);
    split2<<<(LL * 3 * CC * CC) / 256, 256>>>(w_hh, p_whhhi, p_whhlo);
    split2<<<HSZ / 256, 256>>>(x, p_hAhi, p_hAlo);   // h0 = x

    // layer-0 hw from x splits (only standalone hw GEMM)
    wmma2_hw<<<dim3(ROWS / 128, 1, 1), 256, SMEM_HW>>>(
        p_wThi, p_wTlo, p_hAhi, p_hAlo,
        p_hwhi, p_hwlo, CC, CC, CC, ROWS);

    __half* hs_hi[2] = { p_hAhi, p_hBhi };
    __half* hs_lo[2] = { p_hAlo, p_hBlo };

    for (int l = 0; l < LL; l++) {
        __half* chi = hs_hi[l & 1];
        __half* clo = hs_lo[l & 1];
        __half* nhi = hs_hi[(l + 1) & 1];
        __half* nlo = hs_lo[(l + 1) & 1];
        const long loffG = (long)l * 3 * CC * CC;
        const long loffWn = (long)(l + 1 < LL ? l + 1 : 0) * CC * CC;

        // 1) fused: m = adjT @ (hw_hi+hw_lo)  AND  gh = h @ w_hh^T + b_hh
        fused_adj_gh<<<512, 256, SMEM_BIG>>>(
            p_adjT, p_hwhi, p_hwlo, p_mhi, p_mlo,
            chi, clo, p_whhhi + loffG, p_whhlo + loffG,
            p_gh, b_hh + (long)l * 3 * CC);

        // 2) gx = m @ w_ih^T + b_ih
        gate_mma<<<dim3(3, ROWS / 256), 256, SMEM_BIG>>>(
            p_mhi, p_mlo, p_wihhi + loffG, p_wihlo + loffG,
            p_gx, b_ih + (long)l * 3 * CC);

        // 3) fused GRU + next-layer hw GEMM
        gru_hw<<<ROWS / 128, 256, SMEM_GRU>>>(
            p_gx, p_gh, chi, clo, nhi, nlo,
            p_wThi + loffWn, p_wTlo + loffWn,
            p_hwhi, p_hwlo,
            out, mask, (l == LL - 1) ? 1 : 0);
    }
}

// round 13
// speedup vs baseline: 1.3498x; 1.3498x over previous
#include <cuda_runtime.h>
#include <cuda_fp16.h>
#include <cstdint>

// Problem constants: B=32, N=1024, C=128, L=4
#define BB 32
#define NN 1024
#define CC 128
#define LL 4
#define ROWS (BB * NN)          // 32768
#define HSZ  (ROWS * CC)
#define GSZ  (ROWS * 3 * CC)

// fp32 scratch
__device__ __align__(16) float g_gx[GSZ];
__device__ __align__(16) float g_gh[GSZ];
// fp16 scratch
__device__ __align__(16) __half g_adjT[(size_t)BB * NN * NN];   // [b][n][j] exact
__device__ __align__(16) __half g_hwT_hi[HSZ];                  // [d][b*N+j]
__device__ __align__(16) __half g_hwT_lo[HSZ];
__device__ __align__(16) __half g_hA_hi[HSZ];                   // h splits (ping)
__device__ __align__(16) __half g_hA_lo[HSZ];
__device__ __align__(16) __half g_hB_hi[HSZ];                   // h splits (pong)
__device__ __align__(16) __half g_hB_lo[HSZ];
__device__ __align__(16) __half g_mA_hi[HSZ];                   // m splits
__device__ __align__(16) __half g_mA_lo[HSZ];
__device__ __align__(16) __half g_wT_hi[LL * CC * CC];          // [l][d][c]
__device__ __align__(16) __half g_wT_lo[LL * CC * CC];
__device__ __align__(16) __half g_wih_hi[LL * 3 * CC * CC];
__device__ __align__(16) __half g_wih_lo[LL * 3 * CC * CC];
__device__ __align__(16) __half g_whh_hi[LL * 3 * CC * CC];
__device__ __align__(16) __half g_whh_lo[LL * 3 * CC * CC];

// ===========================================================================
// helpers
// ===========================================================================
__device__ __forceinline__ uint32_t smem_u32(const void* p) {
    uint32_t a;
    asm("{ .reg .u64 t; cvta.to.shared.u64 t, %1; cvt.u32.u64 %0, t; }"
        : "=r"(a) : "l"(p));
    return a;
}
__device__ __forceinline__ void cp16(uint32_t s, const void* g) {
    asm volatile("cp.async.cg.shared.global [%0], [%1], 16;" :: "r"(s), "l"(g));
}
#define CP_COMMIT() asm volatile("cp.async.commit_group;" ::: "memory")
#define CP_WAIT(n)  asm volatile("cp.async.wait_group %0;" :: "n"(n) : "memory")

#define LDSM4(R0, R1, R2, R3, ADDR)                                          \
    asm volatile("ldmatrix.sync.aligned.m8n8.x4.shared.b16 {%0,%1,%2,%3}, [%4];" \
                 : "=r"(R0), "=r"(R1), "=r"(R2), "=r"(R3) : "r"(ADDR))

#define MMA16816(D, A, B0, B1)                                               \
    asm volatile(                                                            \
        "mma.sync.aligned.m16n8k16.row.col.f32.f16.f16.f32 "                 \
        "{%0,%1,%2,%3},{%4,%5,%6,%7},{%8,%9},{%0,%1,%2,%3};"                 \
        : "+f"((D)[0]), "+f"((D)[1]), "+f"((D)[2]), "+f"((D)[3])             \
        : "r"((A)[0]), "r"((A)[1]), "r"((A)[2]), "r"((A)[3]),                \
          "r"(B0), "r"(B1))

// Load an R-row x 64-col fp16 tile (128B rows, XOR-16B swizzle) via cp.async.
template <int R>
__device__ __forceinline__ void cp_tile(const __half* __restrict__ g,
                                        int stride, uint32_t sdst, int t, int kc)
{
    #pragma unroll
    for (int u = 0; u < R / 32; ++u) {
        const int unit = t + u * 256;
        const int row  = unit >> 3;
        const int c16  = unit & 7;
        const uint32_t sw = ((row << 7) + (c16 << 4)) ^ ((row & 7) << 4);
        cp16(sdst + sw, g + (size_t)row * stride + (kc << 6) + (c16 << 3));
    }
}

// ===========================================================================
// fused adj + gh kernel (R11 verbatim).
// CTAs [0,128):   m[b][n][d] = adjT[b] @ (hw_hi+hw_lo)   (3-stage pipeline)
// CTAs [128,512): gh = h @ w_hh^T + b_hh                 (2-stage, 3-product)
// ===========================================================================
__global__ __launch_bounds__(256)
void fused_adj_gh(const __half* __restrict__ adjT,
                  const __half* __restrict__ hwhi, const __half* __restrict__ hwlo,
                  __half* __restrict__ mhi, __half* __restrict__ mlo,
                  const __half* __restrict__ hhi, const __half* __restrict__ hlo,
                  const __half* __restrict__ whh_hi, const __half* __restrict__ whh_lo,
                  float* __restrict__ gh, const float* __restrict__ bias_hh)
{
    extern __shared__ __align__(128) char smem[];
    const uint32_t sbase = smem_u32(smem);

    const int t     = threadIdx.x;
    const int lane  = t & 31;
    const int warp  = t >> 5;
    const int mwarp = (warp >> 1) * 64;
    const int nwarp = (warp & 1) * 64;

    if (blockIdx.x < 128) {
        constexpr uint32_t ATSZ = 32768;
        constexpr uint32_t BTSZ = 16384;
        constexpr uint32_t STG  = ATSZ + 2 * BTSZ;

        const int mtile = blockIdx.x & 3;
        const int z     = blockIdx.x >> 2;
        const int m0    = mtile * 256;

        const __half* Ag = adjT + (size_t)z * NN * NN + (size_t)m0 * NN;
        const __half* Bh = hwhi + (size_t)z * NN;
        const __half* Bl = hwlo + (size_t)z * NN;

        constexpr int NC = NN >> 6;

        float acc[4][8][4];
        #pragma unroll
        for (int i = 0; i < 4; i++)
            #pragma unroll
            for (int j = 0; j < 8; j++)
                #pragma unroll
                for (int q = 0; q < 4; q++)
                    acc[i][j][q] = 0.0f;

        auto load_stage = [&](int kc, uint32_t sb) {
            cp_tile<256>(Ag, NN, sb, t, kc);
            cp_tile<128>(Bh, ROWS, sb + ATSZ, t, kc);
            cp_tile<128>(Bl, ROWS, sb + ATSZ + BTSZ, t, kc);
            CP_COMMIT();
        };

        load_stage(0, sbase);
        load_stage(1, sbase + STG);

        for (int c = 0; c < NC; ++c) {
            const int nxt = c + 2;
            if (nxt < NC) load_stage(nxt, sbase + (nxt % 3) * STG);
            const int nleft = NC - 1 - c;
            if (nleft >= 2)      CP_WAIT(2);
            else if (nleft == 1) CP_WAIT(1);
            else                 CP_WAIT(0);
            __syncthreads();

            const uint32_t S = sbase + (c % 3) * STG;
            const uint32_t Bb = S + ATSZ;

            #pragma unroll
            for (int ks = 0; ks < 4; ++ks) {
                uint32_t ah[4][4];
                #pragma unroll
                for (int mb = 0; mb < 4; ++mb) {
                    const int row = mwarp + mb * 16 + (lane & 15);
                    const int col = ks * 32 + ((lane >> 4) << 4);
                    const uint32_t sw = (row << 7) + (col ^ ((row & 7) << 4));
                    LDSM4(ah[mb][0], ah[mb][1], ah[mb][2], ah[mb][3], S + sw);
                }
                uint32_t bh[4][4], bl[4][4];
                #pragma unroll
                for (int nq = 0; nq < 4; ++nq) {
                    const int row = nwarp + nq * 16 + ((lane >> 4) << 3) + (lane & 7);
                    const int col = ks * 32 + (((lane >> 3) & 1) << 4);
                    const uint32_t sw = (row << 7) + (col ^ ((row & 7) << 4));
                    LDSM4(bh[nq][0], bh[nq][1], bh[nq][2], bh[nq][3], Bb + sw);
                    LDSM4(bl[nq][0], bl[nq][1], bl[nq][2], bl[nq][3], Bb + BTSZ + sw);
                }
                #pragma unroll
                for (int mb = 0; mb < 4; ++mb)
                    #pragma unroll
                    for (int n = 0; n < 8; ++n) {
                        const int q0 = (n & 1) * 2;
                        MMA16816(acc[mb][n], ah[mb], bh[n >> 1][q0], bh[n >> 1][q0 + 1]);
                        MMA16816(acc[mb][n], ah[mb], bl[n >> 1][q0], bl[n >> 1][q0 + 1]);
                    }
            }
            __syncthreads();
        }

        const int rbase = m0 + mwarp + (lane >> 2);
        const int cbase = nwarp + (lane & 3) * 2;
        __half* CH = mhi + (size_t)z * NN * CC;
        __half* CL = mlo + (size_t)z * NN * CC;
        #pragma unroll
        for (int mb = 0; mb < 4; ++mb) {
            #pragma unroll
            for (int n = 0; n < 8; ++n) {
                const int gc = cbase + n * 8;
                const int r  = rbase + mb * 16;
                #pragma unroll
                for (int hf = 0; hf < 2; ++hf) {
                    const float v0 = acc[mb][n][hf * 2 + 0];
                    const float v1 = acc[mb][n][hf * 2 + 1];
                    const __half h0 = __float2half_rn(v0);
                    const __half h1 = __float2half_rn(v1);
                    __half2 ph; ph.x = h0; ph.y = h1;
                    __half2 pl;
                    pl.x = __float2half_rn(v0 - __half2float(h0));
                    pl.y = __float2half_rn(v1 - __half2float(h1));
                    const size_t off = (size_t)(r + hf * 8) * CC + gc;
                    *reinterpret_cast<__half2*>(&CH[off]) = ph;
                    *reinterpret_cast<__half2*>(&CL[off]) = pl;
                }
            }
        }
    } else {
        constexpr uint32_t ATSZ = 32768;
        constexpr uint32_t BTSZ = 16384;
        constexpr uint32_t STG  = 2 * ATSZ + 2 * BTSZ;

        const int id = blockIdx.x - 128;
        const int n0 = (id % 3) * 128;
        const int m0 = (id / 3) * 256;

        const __half* Ah = hhi + (size_t)m0 * CC;
        const __half* Al = hlo + (size_t)m0 * CC;
        const __half* Bh = whh_hi + (size_t)n0 * CC;
        const __half* Bl = whh_lo + (size_t)n0 * CC;

        constexpr int NC = 2;

        float acc[4][8][4];
        #pragma unroll
        for (int i = 0; i < 4; i++)
            #pragma unroll
            for (int j = 0; j < 8; j++)
                #pragma unroll
                for (int q = 0; q < 4; q++)
                    acc[i][j][q] = 0.0f;

        auto load_stage = [&](int kc, uint32_t sb) {
            cp_tile<256>(Ah, CC, sb, t, kc);
            cp_tile<256>(Al, CC, sb + ATSZ, t, kc);
            cp_tile<128>(Bh, CC, sb + 2 * ATSZ, t, kc);
            cp_tile<128>(Bl, CC, sb + 2 * ATSZ + BTSZ, t, kc);
            CP_COMMIT();
        };

        load_stage(0, sbase);
        load_stage(1, sbase + STG);

        #pragma unroll
        for (int c = 0; c < NC; ++c) {
            if (c == 0) CP_WAIT(1); else CP_WAIT(0);
            __syncthreads();

            const uint32_t S = sbase + c * STG;
            const uint32_t Bb = S + 2 * ATSZ;

            #pragma unroll
            for (int ks = 0; ks < 4; ++ks) {
                uint32_t ah[4][4], al[4][4];
                #pragma unroll
                for (int mb = 0; mb < 4; ++mb) {
                    const int row = mwarp + mb * 16 + (lane & 15);
                    const int col = ks * 32 + ((lane >> 4) << 4);
                    const uint32_t sw = (row << 7) + (col ^ ((row & 7) << 4));
                    LDSM4(ah[mb][0], ah[mb][1], ah[mb][2], ah[mb][3], S + sw);
                    LDSM4(al[mb][0], al[mb][1], al[mb][2], al[mb][3], S + ATSZ + sw);
                }
                uint32_t bh[4][4], bl[4][4];
                #pragma unroll
                for (int nq = 0; nq < 4; ++nq) {
                    const int row = nwarp + nq * 16 + ((lane >> 4) << 3) + (lane & 7);
                    const int col = ks * 32 + (((lane >> 3) & 1) << 4);
                    const uint32_t sw = (row << 7) + (col ^ ((row & 7) << 4));
                    LDSM4(bh[nq][0], bh[nq][1], bh[nq][2], bh[nq][3], Bb + sw);
                    LDSM4(bl[nq][0], bl[nq][1], bl[nq][2], bl[nq][3], Bb + BTSZ + sw);
                }
                #pragma unroll
                for (int mb = 0; mb < 4; ++mb)
                    #pragma unroll
                    for (int n = 0; n < 8; ++n) {
                        const int q0 = (n & 1) * 2;
                        MMA16816(acc[mb][n], ah[mb], bh[n >> 1][q0], bh[n >> 1][q0 + 1]);
                        MMA16816(acc[mb][n], ah[mb], bl[n >> 1][q0], bl[n >> 1][q0 + 1]);
                        MMA16816(acc[mb][n], al[mb], bh[n >> 1][q0], bh[n >> 1][q0 + 1]);
                    }
            }
            __syncthreads();
        }

        const int rbase = m0 + mwarp + (lane >> 2);
        const int cbase = n0 + nwarp + (lane & 3) * 2;
        #pragma unroll
        for (int mb = 0; mb < 4; ++mb) {
            #pragma unroll
            for (int n = 0; n < 8; ++n) {
                const int gc = cbase + n * 8;
                const float bx = bias_hh[gc];
                const float by = bias_hh[gc + 1];
                const int r = rbase + mb * 16;
                float2 v0 = { acc[mb][n][0] + bx, acc[mb][n][1] + by };
                float2 v1 = { acc[mb][n][2] + bx, acc[mb][n][3] + by };
                *reinterpret_cast<float2*>(&gh[(size_t)r * (3 * CC) + gc])       = v0;
                *reinterpret_cast<float2*>(&gh[(size_t)(r + 8) * (3 * CC) + gc]) = v1;
            }
        }
    }
}

// ===========================================================================
// gate_mma: gx = m @ w_ih^T + b_ih  (3-product, fp32 out, ldc=384)
// ===========================================================================
__global__ __launch_bounds__(256)
void gate_mma(const __half* __restrict__ a_hi, const __half* __restrict__ a_lo,
              const __half* __restrict__ b_hi, const __half* __restrict__ b_lo,
              float* __restrict__ C, const float* __restrict__ bias)
{
    constexpr uint32_t ATSZ = 32768;
    constexpr uint32_t BTSZ = 16384;
    constexpr uint32_t STG  = 2 * ATSZ + 2 * BTSZ;
    extern __shared__ __align__(128) char smem[];
    const uint32_t sbase = smem_u32(smem);

    const int t     = threadIdx.x;
    const int lane  = t & 31;
    const int warp  = t >> 5;
    const int mwarp = (warp >> 1) * 64;
    const int nwarp = (warp & 1) * 64;
    const int m0 = blockIdx.y * 256;
    const int n0 = blockIdx.x * 128;

    const __half* Ah = a_hi + (size_t)m0 * CC;
    const __half* Al = a_lo + (size_t)m0 * CC;
    const __half* Bh = b_hi + (size_t)n0 * CC;
    const __half* Bl = b_lo + (size_t)n0 * CC;

    constexpr int NC = 2;

    float acc[4][8][4];
    #pragma unroll
    for (int i = 0; i < 4; i++)
        #pragma unroll
        for (int j = 0; j < 8; j++)
            #pragma unroll
            for (int q = 0; q < 4; q++)
                acc[i][j][q] = 0.0f;

    auto load_stage = [&](int kc, uint32_t sb) {
        cp_tile<256>(Ah, CC, sb, t, kc);
        cp_tile<256>(Al, CC, sb + ATSZ, t, kc);
        cp_tile<128>(Bh, CC, sb + 2 * ATSZ, t, kc);
        cp_tile<128>(Bl, CC, sb + 2 * ATSZ + BTSZ, t, kc);
        CP_COMMIT();
    };

    load_stage(0, sbase);
    load_stage(1, sbase + STG);

    #pragma unroll
    for (int c = 0; c < NC; ++c) {
        if (c == 0) CP_WAIT(1); else CP_WAIT(0);
        __syncthreads();

        const uint32_t S = sbase + c * STG;
        const uint32_t Bb = S + 2 * ATSZ;

        #pragma unroll
        for (int ks = 0; ks < 4; ++ks) {
            uint32_t ah[4][4], al[4][4];
            #pragma unroll
            for (int mb = 0; mb < 4; ++mb) {
                const int row = mwarp + mb * 16 + (lane & 15);
                const int col = ks * 32 + ((lane >> 4) << 4);
                const uint32_t sw = (row << 7) + (col ^ ((row & 7) << 4));
                LDSM4(ah[mb][0], ah[mb][1], ah[mb][2], ah[mb][3], S + sw);
                LDSM4(al[mb][0], al[mb][1], al[mb][2], al[mb][3], S + ATSZ + sw);
            }
            uint32_t bh[4][4], bl[4][4];
            #pragma unroll
            for (int nq = 0; nq < 4; ++nq) {
                const int row = nwarp + nq * 16 + ((lane >> 4) << 3) + (lane & 7);
                const int col = ks * 32 + (((lane >> 3) & 1) << 4);
                const uint32_t sw = (row << 7) + (col ^ ((row & 7) << 4));
                LDSM4(bh[nq][0], bh[nq][1], bh[nq][2], bh[nq][3], Bb + sw);
                LDSM4(bl[nq][0], bl[nq][1], bl[nq][2], bl[nq][3], Bb + BTSZ + sw);
            }
            #pragma unroll
            for (int mb = 0; mb < 4; ++mb)
                #pragma unroll
                for (int n = 0; n < 8; ++n) {
                    const int q0 = (n & 1) * 2;
                    MMA16816(acc[mb][n], ah[mb], bh[n >> 1][q0], bh[n >> 1][q0 + 1]);
                    MMA16816(acc[mb][n], ah[mb], bl[n >> 1][q0], bl[n >> 1][q0 + 1]);
                    MMA16816(acc[mb][n], al[mb], bh[n >> 1][q0], bh[n >> 1][q0 + 1]);
                }
        }
        __syncthreads();
    }

    const int rbase = m0 + mwarp + (lane >> 2);
    const int cbase = n0 + nwarp + (lane & 3) * 2;
    #pragma unroll
    for (int mb = 0; mb < 4; ++mb) {
        #pragma unroll
        for (int n = 0; n < 8; ++n) {
            const int gc = cbase + n * 8;
            const float bx = bias[gc];
            const float by = bias[gc + 1];
            const int r = rbase + mb * 16;
            float2 v0 = { acc[mb][n][0] + bx, acc[mb][n][1] + by };
            float2 v1 = { acc[mb][n][2] + bx, acc[mb][n][3] + by };
            *reinterpret_cast<float2*>(&C[(size_t)r * (3 * CC) + gc])       = v0;
            *reinterpret_cast<float2*>(&C[(size_t)(r + 8) * (3 * CC) + gc]) = v1;
        }
    }
}

// ===========================================================================
// wmma2_hw (128x128 CTA): 3-product fp16 split GEMM for hw.
// ===========================================================================
__global__ __launch_bounds__(256)
void wmma2_hw(const __half* __restrict__ a_hi, const __half* __restrict__ a_lo,
              const __half* __restrict__ b_hi, const __half* __restrict__ b_lo,
              __half* __restrict__ Chi, __half* __restrict__ Clo,
              int K, int lda, int ldb, int ldc)
{
    constexpr uint32_t TSZ = 16384;
    constexpr uint32_t STG = 4 * TSZ;
    extern __shared__ __align__(128) char smem[];
    const uint32_t sbase = smem_u32(smem);

    const int t     = threadIdx.x;
    const int lane  = t & 31;
    const int warp  = t >> 5;
    const int mwarp = (warp >> 1) * 32;
    const int nwarp = (warp & 1) * 64;
    const int m0 = blockIdx.y * 128;
    const int n0 = blockIdx.x * 128;

    const __half* Ah = a_hi + (size_t)m0 * lda;
    const __half* Al = a_lo + (size_t)m0 * lda;
    const __half* Bh = b_hi + (size_t)n0 * ldb;
    const __half* Bl = b_lo + (size_t)n0 * ldb;

    const int NC = K >> 6;

    float acc[2][8][4];
    #pragma unroll
    for (int i = 0; i < 2; i++)
        #pragma unroll
        for (int j = 0; j < 8; j++)
            #pragma unroll
            for (int q = 0; q < 4; q++)
                acc[i][j][q] = 0.0f;

    auto load_stage = [&](int kc, uint32_t sb) {
        cp_tile<128>(Ah, lda, sb, t, kc);
        cp_tile<128>(Al, lda, sb + TSZ, t, kc);
        cp_tile<128>(Bh, ldb, sb + 2 * TSZ, t, kc);
        cp_tile<128>(Bl, ldb, sb + 3 * TSZ, t, kc);
        CP_COMMIT();
    };

    load_stage(0, sbase);

    for (int c = 0; c < NC; ++c) {
        const int buf = c & 1;
        if (c + 1 < NC) {
            load_stage(c + 1, sbase + ((c + 1) & 1) * STG);
            CP_WAIT(1);
        } else {
            CP_WAIT(0);
        }
        __syncthreads();

        const uint32_t S = sbase + buf * STG;

        #pragma unroll
        for (int ks = 0; ks < 4; ++ks) {
            uint32_t ah[2][4], al[2][4];
            #pragma unroll
            for (int mb = 0; mb < 2; ++mb) {
                const int row = mwarp + mb * 16 + (lane & 15);
                const int col = ks * 32 + ((lane >> 4) << 4);
                const uint32_t sw = (row << 7) + (col ^ ((row & 7) << 4));
                LDSM4(ah[mb][0], ah[mb][1], ah[mb][2], ah[mb][3], S + sw);
                LDSM4(al[mb][0], al[mb][1], al[mb][2], al[mb][3], S + TSZ + sw);
            }
            uint32_t bh[4][4], bl[4][4];
            #pragma unroll
            for (int nq = 0; nq < 4; ++nq) {
                const int row = nwarp + nq * 16 + ((lane >> 4) << 3) + (lane & 7);
                const int col = ks * 32 + (((lane >> 3) & 1) << 4);
                const uint32_t sw = (row << 7) + (col ^ ((row & 7) << 4));
                LDSM4(bh[nq][0], bh[nq][1], bh[nq][2], bh[nq][3], S + 2 * TSZ + sw);
                LDSM4(bl[nq][0], bl[nq][1], bl[nq][2], bl[nq][3], S + 3 * TSZ + sw);
            }
            #pragma unroll
            for (int mb = 0; mb < 2; ++mb)
                #pragma unroll
                for (int n = 0; n < 8; ++n) {
                    const int q0 = (n & 1) * 2;
                    MMA16816(acc[mb][n], ah[mb], bh[n >> 1][q0], bh[n >> 1][q0 + 1]);
                    MMA16816(acc[mb][n], ah[mb], bl[n >> 1][q0], bl[n >> 1][q0 + 1]);
                    MMA16816(acc[mb][n], al[mb], bh[n >> 1][q0], bh[n >> 1][q0 + 1]);
                }
        }
        __syncthreads();
    }

    const int rbase = m0 + mwarp + (lane >> 2);
    const int cbase = n0 + nwarp + (lane & 3) * 2;
    #pragma unroll
    for (int mb = 0; mb < 2; ++mb) {
        #pragma unroll
        for (int n = 0; n < 8; ++n) {
            const int gc = cbase + n * 8;
            const int r  = rbase + mb * 16;
            #pragma unroll
            for (int hf = 0; hf < 2; ++hf) {
                const float v0 = acc[mb][n][hf * 2 + 0];
                const float v1 = acc[mb][n][hf * 2 + 1];
                const __half h0 = __float2half_rn(v0);
                const __half h1 = __float2half_rn(v1);
                __half2 ph; ph.x = h0; ph.y = h1;
                __half2 pl;
                pl.x = __float2half_rn(v0 - __half2float(h0));
                pl.y = __float2half_rn(v1 - __half2float(h1));
                const size_t off = (size_t)(r + hf * 8) * ldc + gc;
                *reinterpret_cast<__half2*>(&Chi[off]) = ph;
                *reinterpret_cast<__half2*>(&Clo[off]) = pl;
            }
        }
    }
}

// ===========================================================================
// Prep kernels
// ===========================================================================
__global__ __launch_bounds__(256)
void adj_transpose(const float* __restrict__ adj, __half* __restrict__ adjT)
{
    __shared__ float tile[32][33];
    const int b  = blockIdx.z;
    const int j0 = blockIdx.x * 32;
    const int n0 = blockIdx.y * 32;
    const float* src = adj + (size_t)b * NN * NN;
    __half* dst = adjT + (size_t)b * NN * NN;
    const int tx = threadIdx.x & 31, ty = threadIdx.x >> 5;
    #pragma unroll
    for (int r = ty; r < 32; r += 8)
        tile[r][tx] = src[(size_t)(j0 + r) * NN + n0 + tx];
    __syncthreads();
    #pragma unroll
    for (int r = ty; r < 32; r += 8)
        dst[(size_t)(n0 + r) * NN + j0 + tx] = __float2half_rn(tile[tx][r]);
}

__global__ __launch_bounds__(256)
void split2(const float* __restrict__ x,
            __half* __restrict__ hi, __half* __restrict__ lo)
{
    const int i = blockIdx.x * blockDim.x + threadIdx.x;
    const float v = x[i];
    const __half h = __float2half_rn(v);
    hi[i] = h;
    lo[i] = __float2half_rn(v - __half2float(h));
}

// merged gate-weight splits: z=0 -> w_ih, z=1 -> w_hh
__global__ __launch_bounds__(256)
void split2_gatew(const float* __restrict__ w_ih, const float* __restrict__ w_hh,
                  __half* __restrict__ ih_hi, __half* __restrict__ ih_lo,
                  __half* __restrict__ hh_hi, __half* __restrict__ hh_lo)
{
    const int i = blockIdx.x * blockDim.x + threadIdx.x;
    const float* src = blockIdx.y == 0 ? w_ih : w_hh;
    __half* dhi = blockIdx.y == 0 ? ih_hi : hh_hi;
    __half* dlo = blockIdx.y == 0 ? ih_lo : hh_lo;
    const float v = src[i];
    const __half h = __float2half_rn(v);
    dhi[i] = h;
    dlo[i] = __float2half_rn(v - __half2float(h));
}

// weight[l] fp32 [C][C] (W[c][d]) -> WT hi/lo fp16 [l][d][c]
__global__ __launch_bounds__(256)
void wT_split(const float* __restrict__ W,
              __half* __restrict__ hi, __half* __restrict__ lo)
{
    __shared__ float tile[32][33];
    const int l  = blockIdx.z;
    const int c0 = blockIdx.x * 32;
    const int d0 = blockIdx.y * 32;
    const float* src = W + (size_t)l * CC * CC;
    const size_t ob = (size_t)l * CC * CC;
    const int tx = threadIdx.x & 31, ty = threadIdx.x >> 5;
    #pragma unroll
    for (int r = ty; r < 32; r += 8)
        tile[r][tx] = src[(size_t)(c0 + r) * CC + d0 + tx];
    __syncthreads();
    #pragma unroll
    for (int r = ty; r < 32; r += 8) {
        const float v = tile[tx][r];
        const __half h = __float2half_rn(v);
        hi[ob + (size_t)(d0 + r) * CC + c0 + tx] = h;
        lo[ob + (size_t)(d0 + r) * CC + c0 + tx] = __float2half_rn(v - __half2float(h));
    }
}

// ===========================================================================
// Fused GRU elementwise (vectorized: 2 channels per thread).
// ===========================================================================
__global__ __launch_bounds__(256)
void gru_elem4(const float* __restrict__ gx, const float* __restrict__ gh,
               const __half* __restrict__ hhi_in, const __half* __restrict__ hlo_in,
               __half* __restrict__ hhi_out, __half* __restrict__ hlo_out,
               float* __restrict__ outF,
               const float* __restrict__ mask, int isLast)
{
    const int u  = blockIdx.x * blockDim.x + threadIdx.x;   // < ROWS*CC/2
    const int r  = u >> 6;             // row
    const int c0 = (u & 63) * 2;       // even channel
    const size_t idx = (size_t)r * CC + c0;
    const size_t gb  = (size_t)r * (3 * CC);

    const float2 xr = *reinterpret_cast<const float2*>(&gx[gb + c0]);
    const float2 xz = *reinterpret_cast<const float2*>(&gx[gb + CC + c0]);
    const float2 xn = *reinterpret_cast<const float2*>(&gx[gb + 2 * CC + c0]);
    const float2 hr = *reinterpret_cast<const float2*>(&gh[gb + c0]);
    const float2 hz = *reinterpret_cast<const float2*>(&gh[gb + CC + c0]);
    const float2 hn = *reinterpret_cast<const float2*>(&gh[gb + 2 * CC + c0]);
    const __half2 hh = *reinterpret_cast<const __half2*>(&hhi_in[idx]);
    const __half2 hl = *reinterpret_cast<const __half2*>(&hlo_in[idx]);
    const float h0 = __half2float(hh.x) + __half2float(hl.x);
    const float h1 = __half2float(hh.y) + __half2float(hl.y);

    const float rg0 = 1.0f / (1.0f + __expf(-(xr.x + hr.x)));
    const float rg1 = 1.0f / (1.0f + __expf(-(xr.y + hr.y)));
    const float zg0 = 1.0f / (1.0f + __expf(-(xz.x + hz.x)));
    const float zg1 = 1.0f / (1.0f + __expf(-(xz.y + hz.y)));
    const float ng0 = tanhf(xn.x + rg0 * hn.x);
    const float ng1 = tanhf(xn.y + rg1 * hn.y);
    const float hnew0 = (1.0f - zg0) * ng0 + zg0 * h0;
    const float hnew1 = (1.0f - zg1) * ng1 + zg1 * h1;

    if (isLast) {
        const float mk = mask[r];
        float2 o = { hnew0 * mk, hnew1 * mk };
        *reinterpret_cast<float2*>(&outF[idx]) = o;
    } else {
        const __half H0 = __float2half_rn(hnew0);
        const __half H1 = __float2half_rn(hnew1);
        __half2 ph; ph.x = H0; ph.y = H1;
        __half2 pl;
        pl.x = __float2half_rn(hnew0 - __half2float(H0));
        pl.y = __float2half_rn(hnew1 - __half2float(H1));
        *reinterpret_cast<__half2*>(&hhi_out[idx]) = ph;
        *reinterpret_cast<__half2*>(&hlo_out[idx]) = pl;
    }
}

// ===========================================================================
#define SMEM_BIG   (3 * (32768 + 2 * 16384))         // 192 KB
#define SMEM_HW    (2 * 4 * 16384)                   // 128 KB

extern "C" void kernel_launch(void* const* d_in, const int* in_sizes, int n_in,
                              void* d_out, int out_size)
{
    const float* x      = (const float*)d_in[0];
    const float* adj    = (const float*)d_in[1];
    const float* mask   = (const float*)d_in[2];
    const float* weight = (const float*)d_in[3];
    const float* w_ih   = (const float*)d_in[4];
    const float* w_hh   = (const float*)d_in[5];
    const float* b_ih   = (const float*)d_in[6];
    const float* b_hh   = (const float*)d_in[7];
    float* out = (float*)d_out;

    float *p_gx, *p_gh;
    __half *p_adjT, *p_hwhi, *p_hwlo, *p_mhi, *p_mlo;
    __half *p_hAhi, *p_hAlo, *p_hBhi, *p_hBlo;
    __half *p_wThi, *p_wTlo, *p_wihhi, *p_wihlo, *p_whhhi, *p_whhlo;
    cudaGetSymbolAddress((void**)&p_gx, g_gx);
    cudaGetSymbolAddress((void**)&p_gh, g_gh);
    cudaGetSymbolAddress((void**)&p_adjT, g_adjT);
    cudaGetSymbolAddress((void**)&p_hwhi, g_hwT_hi);
    cudaGetSymbolAddress((void**)&p_hwlo, g_hwT_lo);
    cudaGetSymbolAddress((void**)&p_mhi, g_mA_hi);
    cudaGetSymbolAddress((void**)&p_mlo, g_mA_lo);
    cudaGetSymbolAddress((void**)&p_hAhi, g_hA_hi);
    cudaGetSymbolAddress((void**)&p_hAlo, g_hA_lo);
    cudaGetSymbolAddress((void**)&p_hBhi, g_hB_hi);
    cudaGetSymbolAddress((void**)&p_hBlo, g_hB_lo);
    cudaGetSymbolAddress((void**)&p_wThi, g_wT_hi);
    cudaGetSymbolAddress((void**)&p_wTlo, g_wT_lo);
    cudaGetSymbolAddress((void**)&p_wihhi, g_wih_hi);
    cudaGetSymbolAddress((void**)&p_wihlo, g_wih_lo);
    cudaGetSymbolAddress((void**)&p_whhhi, g_whh_hi);
    cudaGetSymbolAddress((void**)&p_whhlo, g_whh_lo);

    cudaFuncSetAttribute(fused_adj_gh, cudaFuncAttributeMaxDynamicSharedMemorySize, SMEM_BIG);
    cudaFuncSetAttribute(gate_mma,     cudaFuncAttributeMaxDynamicSharedMemorySize, SMEM_BIG);
    cudaFuncSetAttribute(wmma2_hw,     cudaFuncAttributeMaxDynamicSharedMemorySize, SMEM_HW);

    // ---- once per call ----
    adj_transpose<<<dim3(NN / 32, NN / 32, BB), 256>>>(adj, p_adjT);
    wT_split<<<dim3(CC / 32, CC / 32, LL), 256>>>(weight, p_wThi, p_wTlo);
    split2_gatew<<<dim3((LL * 3 * CC * CC) / 256, 2), 256>>>(
        w_ih, w_hh, p_wihhi, p_wihlo, p_whhhi, p_whhlo);
    split2<<<HSZ / 256, 256>>>(x, p_hAhi, p_hAlo);   // h0 = x

    __half* hs_hi[2] = { p_hAhi, p_hBhi };
    __half* hs_lo[2] = { p_hAlo, p_hBlo };

    for (int l = 0; l < LL; l++) {
        __half* chi = hs_hi[l & 1];
        __half* clo = hs_lo[l & 1];
        __half* nhi = hs_hi[(l + 1) & 1];
        __half* nlo = hs_lo[(l + 1) & 1];
        const long loffW = (long)l * CC * CC;
        const long loffG = (long)l * 3 * CC * CC;

        // 1) hwT[d][b*N+j] = sum_c WT[d][c] * h[j][c]   (3-product)
        wmma2_hw<<<dim3(ROWS / 128, 1, 1), 256, SMEM_HW>>>(
            p_wThi + loffW, p_wTlo + loffW, chi, clo,
            p_hwhi, p_hwlo, CC, CC, CC, ROWS);

        // 2) fused: m = adjT @ (hw_hi+hw_lo)  AND  gh = h @ w_hh^T + b_hh
        fused_adj_gh<<<512, 256, SMEM_BIG>>>(
            p_adjT, p_hwhi, p_hwlo, p_mhi, p_mlo,
            chi, clo, p_whhhi + loffG, p_whhlo + loffG,
            p_gh, b_hh + (long)l * 3 * CC);

        // 3) gx = m @ w_ih^T + b_ih
        gate_mma<<<dim3(3, ROWS / 256), 256, SMEM_BIG>>>(
            p_mhi, p_mlo, p_wihhi + loffG, p_wihlo + loffG,
            p_gx, b_ih + (long)l * 3 * CC);

        // 4) GRU elementwise (vectorized, 2 ch/thread)
        gru_elem4<<<(ROWS * CC / 2) / 256, 256>>>(
            p_gx, p_gh, chi, clo, nhi, nlo, out, mask, (l == LL - 1) ? 1 : 0);
    }
}

// round 14
// speedup vs baseline: 1.3937x; 1.0325x over previous
#include <cuda_runtime.h>
#include <cuda_fp16.h>
#include <cstdint>

// Problem constants: B=32, N=1024, C=128, L=4
#define BB 32
#define NN 1024
#define CC 128
#define LL 4
#define ROWS (BB * NN)          // 32768
#define HSZ  (ROWS * CC)
#define GSZ  (ROWS * 3 * CC)

// fp32 scratch
__device__ __align__(16) float g_gx[GSZ];
__device__ __align__(16) float g_gh[GSZ];
// fp16 scratch
__device__ __align__(16) __half g_adjT[(size_t)BB * NN * NN];   // [b][n][j] exact
__device__ __align__(16) __half g_hwT_hi[HSZ];                  // [d][b*N+j]
__device__ __align__(16) __half g_hwT_lo[HSZ];
__device__ __align__(16) __half g_hA_hi[HSZ];                   // h splits (ping)
__device__ __align__(16) __half g_hA_lo[HSZ];
__device__ __align__(16) __half g_hB_hi[HSZ];                   // h splits (pong)
__device__ __align__(16) __half g_hB_lo[HSZ];
__device__ __align__(16) __half g_mA_hi[HSZ];                   // m splits
__device__ __align__(16) __half g_mA_lo[HSZ];
__device__ __align__(16) __half g_wT_hi[LL * CC * CC];          // [l][d][c]
__device__ __align__(16) __half g_wT_lo[LL * CC * CC];
__device__ __align__(16) __half g_wih_hi[LL * 3 * CC * CC];
__device__ __align__(16) __half g_wih_lo[LL * 3 * CC * CC];
__device__ __align__(16) __half g_whh_hi[LL * 3 * CC * CC];
__device__ __align__(16) __half g_whh_lo[LL * 3 * CC * CC];

// ===========================================================================
// helpers
// ===========================================================================
__device__ __forceinline__ uint32_t smem_u32(const void* p) {
    uint32_t a;
    asm("{ .reg .u64 t; cvta.to.shared.u64 t, %1; cvt.u32.u64 %0, t; }"
        : "=r"(a) : "l"(p));
    return a;
}
__device__ __forceinline__ void cp16(uint32_t s, const void* g) {
    asm volatile("cp.async.cg.shared.global [%0], [%1], 16;" :: "r"(s), "l"(g));
}
#define CP_COMMIT() asm volatile("cp.async.commit_group;" ::: "memory")
#define CP_WAIT(n)  asm volatile("cp.async.wait_group %0;" :: "n"(n) : "memory")

#define LDSM4(R0, R1, R2, R3, ADDR)                                          \
    asm volatile("ldmatrix.sync.aligned.m8n8.x4.shared.b16 {%0,%1,%2,%3}, [%4];" \
                 : "=r"(R0), "=r"(R1), "=r"(R2), "=r"(R3) : "r"(ADDR))

#define MMA16816(D, A, B0, B1)                                               \
    asm volatile(                                                            \
        "mma.sync.aligned.m16n8k16.row.col.f32.f16.f16.f32 "                 \
        "{%0,%1,%2,%3},{%4,%5,%6,%7},{%8,%9},{%0,%1,%2,%3};"                 \
        : "+f"((D)[0]), "+f"((D)[1]), "+f"((D)[2]), "+f"((D)[3])             \
        : "r"((A)[0]), "r"((A)[1]), "r"((A)[2]), "r"((A)[3]),                \
          "r"(B0), "r"(B1))

// Load an R-row x 64-col fp16 tile (128B rows, XOR-16B swizzle) via cp.async.
template <int R>
__device__ __forceinline__ void cp_tile(const __half* __restrict__ g,
                                        int stride, uint32_t sdst, int t, int kc)
{
    #pragma unroll
    for (int u = 0; u < R / 32; ++u) {
        const int unit = t + u * 256;
        const int row  = unit >> 3;
        const int c16  = unit & 7;
        const uint32_t sw = ((row << 7) + (c16 << 4)) ^ ((row & 7) << 4);
        cp16(sdst + sw, g + (size_t)row * stride + (kc << 6) + (c16 << 3));
    }
}

// ===========================================================================
// fused adj + gh kernel (R11 verbatim).
// CTAs [0,128):   m[b][n][d] = adjT[b] @ (hw_hi+hw_lo)   (3-stage pipeline)
// CTAs [128,512): gh = h @ w_hh^T + b_hh                 (2-stage, 3-product)
// ===========================================================================
__global__ __launch_bounds__(256)
void fused_adj_gh(const __half* __restrict__ adjT,
                  const __half* __restrict__ hwhi, const __half* __restrict__ hwlo,
                  __half* __restrict__ mhi, __half* __restrict__ mlo,
                  const __half* __restrict__ hhi, const __half* __restrict__ hlo,
                  const __half* __restrict__ whh_hi, const __half* __restrict__ whh_lo,
                  float* __restrict__ gh, const float* __restrict__ bias_hh)
{
    extern __shared__ __align__(128) char smem[];
    const uint32_t sbase = smem_u32(smem);

    const int t     = threadIdx.x;
    const int lane  = t & 31;
    const int warp  = t >> 5;
    const int mwarp = (warp >> 1) * 64;
    const int nwarp = (warp & 1) * 64;

    if (blockIdx.x < 128) {
        constexpr uint32_t ATSZ = 32768;
        constexpr uint32_t BTSZ = 16384;
        constexpr uint32_t STG  = ATSZ + 2 * BTSZ;

        const int mtile = blockIdx.x & 3;
        const int z     = blockIdx.x >> 2;
        const int m0    = mtile * 256;

        const __half* Ag = adjT + (size_t)z * NN * NN + (size_t)m0 * NN;
        const __half* Bh = hwhi + (size_t)z * NN;
        const __half* Bl = hwlo + (size_t)z * NN;

        constexpr int NC = NN >> 6;

        float acc[4][8][4];
        #pragma unroll
        for (int i = 0; i < 4; i++)
            #pragma unroll
            for (int j = 0; j < 8; j++)
                #pragma unroll
                for (int q = 0; q < 4; q++)
                    acc[i][j][q] = 0.0f;

        auto load_stage = [&](int kc, uint32_t sb) {
            cp_tile<256>(Ag, NN, sb, t, kc);
            cp_tile<128>(Bh, ROWS, sb + ATSZ, t, kc);
            cp_tile<128>(Bl, ROWS, sb + ATSZ + BTSZ, t, kc);
            CP_COMMIT();
        };

        load_stage(0, sbase);
        load_stage(1, sbase + STG);

        for (int c = 0; c < NC; ++c) {
            const int nxt = c + 2;
            if (nxt < NC) load_stage(nxt, sbase + (nxt % 3) * STG);
            const int nleft = NC - 1 - c;
            if (nleft >= 2)      CP_WAIT(2);
            else if (nleft == 1) CP_WAIT(1);
            else                 CP_WAIT(0);
            __syncthreads();

            const uint32_t S = sbase + (c % 3) * STG;
            const uint32_t Bb = S + ATSZ;

            #pragma unroll
            for (int ks = 0; ks < 4; ++ks) {
                uint32_t ah[4][4];
                #pragma unroll
                for (int mb = 0; mb < 4; ++mb) {
                    const int row = mwarp + mb * 16 + (lane & 15);
                    const int col = ks * 32 + ((lane >> 4) << 4);
                    const uint32_t sw = (row << 7) + (col ^ ((row & 7) << 4));
                    LDSM4(ah[mb][0], ah[mb][1], ah[mb][2], ah[mb][3], S + sw);
                }
                uint32_t bh[4][4], bl[4][4];
                #pragma unroll
                for (int nq = 0; nq < 4; ++nq) {
                    const int row = nwarp + nq * 16 + ((lane >> 4) << 3) + (lane & 7);
                    const int col = ks * 32 + (((lane >> 3) & 1) << 4);
                    const uint32_t sw = (row << 7) + (col ^ ((row & 7) << 4));
                    LDSM4(bh[nq][0], bh[nq][1], bh[nq][2], bh[nq][3], Bb + sw);
                    LDSM4(bl[nq][0], bl[nq][1], bl[nq][2], bl[nq][3], Bb + BTSZ + sw);
                }
                #pragma unroll
                for (int mb = 0; mb < 4; ++mb)
                    #pragma unroll
                    for (int n = 0; n < 8; ++n) {
                        const int q0 = (n & 1) * 2;
                        MMA16816(acc[mb][n], ah[mb], bh[n >> 1][q0], bh[n >> 1][q0 + 1]);
                        MMA16816(acc[mb][n], ah[mb], bl[n >> 1][q0], bl[n >> 1][q0 + 1]);
                    }
            }
            __syncthreads();
        }

        const int rbase = m0 + mwarp + (lane >> 2);
        const int cbase = nwarp + (lane & 3) * 2;
        __half* CH = mhi + (size_t)z * NN * CC;
        __half* CL = mlo + (size_t)z * NN * CC;
        #pragma unroll
        for (int mb = 0; mb < 4; ++mb) {
            #pragma unroll
            for (int n = 0; n < 8; ++n) {
                const int gc = cbase + n * 8;
                const int r  = rbase + mb * 16;
                #pragma unroll
                for (int hf = 0; hf < 2; ++hf) {
                    const float v0 = acc[mb][n][hf * 2 + 0];
                    const float v1 = acc[mb][n][hf * 2 + 1];
                    const __half h0 = __float2half_rn(v0);
                    const __half h1 = __float2half_rn(v1);
                    __half2 ph; ph.x = h0; ph.y = h1;
                    __half2 pl;
                    pl.x = __float2half_rn(v0 - __half2float(h0));
                    pl.y = __float2half_rn(v1 - __half2float(h1));
                    const size_t off = (size_t)(r + hf * 8) * CC + gc;
                    *reinterpret_cast<__half2*>(&CH[off]) = ph;
                    *reinterpret_cast<__half2*>(&CL[off]) = pl;
                }
            }
        }
    } else {
        constexpr uint32_t ATSZ = 32768;
        constexpr uint32_t BTSZ = 16384;
        constexpr uint32_t STG  = 2 * ATSZ + 2 * BTSZ;

        const int id = blockIdx.x - 128;
        const int n0 = (id % 3) * 128;
        const int m0 = (id / 3) * 256;

        const __half* Ah = hhi + (size_t)m0 * CC;
        const __half* Al = hlo + (size_t)m0 * CC;
        const __half* Bh = whh_hi + (size_t)n0 * CC;
        const __half* Bl = whh_lo + (size_t)n0 * CC;

        constexpr int NC = 2;

        float acc[4][8][4];
        #pragma unroll
        for (int i = 0; i < 4; i++)
            #pragma unroll
            for (int j = 0; j < 8; j++)
                #pragma unroll
                for (int q = 0; q < 4; q++)
                    acc[i][j][q] = 0.0f;

        auto load_stage = [&](int kc, uint32_t sb) {
            cp_tile<256>(Ah, CC, sb, t, kc);
            cp_tile<256>(Al, CC, sb + ATSZ, t, kc);
            cp_tile<128>(Bh, CC, sb + 2 * ATSZ, t, kc);
            cp_tile<128>(Bl, CC, sb + 2 * ATSZ + BTSZ, t, kc);
            CP_COMMIT();
        };

        load_stage(0, sbase);
        load_stage(1, sbase + STG);

        #pragma unroll
        for (int c = 0; c < NC; ++c) {
            if (c == 0) CP_WAIT(1); else CP_WAIT(0);
            __syncthreads();

            const uint32_t S = sbase + c * STG;
            const uint32_t Bb = S + 2 * ATSZ;

            #pragma unroll
            for (int ks = 0; ks < 4; ++ks) {
                uint32_t ah[4][4], al[4][4];
                #pragma unroll
                for (int mb = 0; mb < 4; ++mb) {
                    const int row = mwarp + mb * 16 + (lane & 15);
                    const int col = ks * 32 + ((lane >> 4) << 4);
                    const uint32_t sw = (row << 7) + (col ^ ((row & 7) << 4));
                    LDSM4(ah[mb][0], ah[mb][1], ah[mb][2], ah[mb][3], S + sw);
                    LDSM4(al[mb][0], al[mb][1], al[mb][2], al[mb][3], S + ATSZ + sw);
                }
                uint32_t bh[4][4], bl[4][4];
                #pragma unroll
                for (int nq = 0; nq < 4; ++nq) {
                    const int row = nwarp + nq * 16 + ((lane >> 4) << 3) + (lane & 7);
                    const int col = ks * 32 + (((lane >> 3) & 1) << 4);
                    const uint32_t sw = (row << 7) + (col ^ ((row & 7) << 4));
                    LDSM4(bh[nq][0], bh[nq][1], bh[nq][2], bh[nq][3], Bb + sw);
                    LDSM4(bl[nq][0], bl[nq][1], bl[nq][2], bl[nq][3], Bb + BTSZ + sw);
                }
                #pragma unroll
                for (int mb = 0; mb < 4; ++mb)
                    #pragma unroll
                    for (int n = 0; n < 8; ++n) {
                        const int q0 = (n & 1) * 2;
                        MMA16816(acc[mb][n], ah[mb], bh[n >> 1][q0], bh[n >> 1][q0 + 1]);
                        MMA16816(acc[mb][n], ah[mb], bl[n >> 1][q0], bl[n >> 1][q0 + 1]);
                        MMA16816(acc[mb][n], al[mb], bh[n >> 1][q0], bh[n >> 1][q0 + 1]);
                    }
            }
            __syncthreads();
        }

        const int rbase = m0 + mwarp + (lane >> 2);
        const int cbase = n0 + nwarp + (lane & 3) * 2;
        #pragma unroll
        for (int mb = 0; mb < 4; ++mb) {
            #pragma unroll
            for (int n = 0; n < 8; ++n) {
                const int gc = cbase + n * 8;
                const float bx = bias_hh[gc];
                const float by = bias_hh[gc + 1];
                const int r = rbase + mb * 16;
                float2 v0 = { acc[mb][n][0] + bx, acc[mb][n][1] + by };
                float2 v1 = { acc[mb][n][2] + bx, acc[mb][n][3] + by };
                *reinterpret_cast<float2*>(&gh[(size_t)r * (3 * CC) + gc])       = v0;
                *reinterpret_cast<float2*>(&gh[(size_t)(r + 8) * (3 * CC) + gc]) = v1;
            }
        }
    }
}

// ===========================================================================
// gate_mma: gx = m @ w_ih^T + b_ih  (3-product, fp32 out, ldc=384)
// ===========================================================================
__global__ __launch_bounds__(256)
void gate_mma(const __half* __restrict__ a_hi, const __half* __restrict__ a_lo,
              const __half* __restrict__ b_hi, const __half* __restrict__ b_lo,
              float* __restrict__ C, const float* __restrict__ bias)
{
    constexpr uint32_t ATSZ = 32768;
    constexpr uint32_t BTSZ = 16384;
    constexpr uint32_t STG  = 2 * ATSZ + 2 * BTSZ;
    extern __shared__ __align__(128) char smem[];
    const uint32_t sbase = smem_u32(smem);

    const int t     = threadIdx.x;
    const int lane  = t & 31;
    const int warp  = t >> 5;
    const int mwarp = (warp >> 1) * 64;
    const int nwarp = (warp & 1) * 64;
    const int m0 = blockIdx.y * 256;
    const int n0 = blockIdx.x * 128;

    const __half* Ah = a_hi + (size_t)m0 * CC;
    const __half* Al = a_lo + (size_t)m0 * CC;
    const __half* Bh = b_hi + (size_t)n0 * CC;
    const __half* Bl = b_lo + (size_t)n0 * CC;

    constexpr int NC = 2;

    float acc[4][8][4];
    #pragma unroll
    for (int i = 0; i < 4; i++)
        #pragma unroll
        for (int j = 0; j < 8; j++)
            #pragma unroll
            for (int q = 0; q < 4; q++)
                acc[i][j][q] = 0.0f;

    auto load_stage = [&](int kc, uint32_t sb) {
        cp_tile<256>(Ah, CC, sb, t, kc);
        cp_tile<256>(Al, CC, sb + ATSZ, t, kc);
        cp_tile<128>(Bh, CC, sb + 2 * ATSZ, t, kc);
        cp_tile<128>(Bl, CC, sb + 2 * ATSZ + BTSZ, t, kc);
        CP_COMMIT();
    };

    load_stage(0, sbase);
    load_stage(1, sbase + STG);

    #pragma unroll
    for (int c = 0; c < NC; ++c) {
        if (c == 0) CP_WAIT(1); else CP_WAIT(0);
        __syncthreads();

        const uint32_t S = sbase + c * STG;
        const uint32_t Bb = S + 2 * ATSZ;

        #pragma unroll
        for (int ks = 0; ks < 4; ++ks) {
            uint32_t ah[4][4], al[4][4];
            #pragma unroll
            for (int mb = 0; mb < 4; ++mb) {
                const int row = mwarp + mb * 16 + (lane & 15);
                const int col = ks * 32 + ((lane >> 4) << 4);
                const uint32_t sw = (row << 7) + (col ^ ((row & 7) << 4));
                LDSM4(ah[mb][0], ah[mb][1], ah[mb][2], ah[mb][3], S + sw);
                LDSM4(al[mb][0], al[mb][1], al[mb][2], al[mb][3], S + ATSZ + sw);
            }
            uint32_t bh[4][4], bl[4][4];
            #pragma unroll
            for (int nq = 0; nq < 4; ++nq) {
                const int row = nwarp + nq * 16 + ((lane >> 4) << 3) + (lane & 7);
                const int col = ks * 32 + (((lane >> 3) & 1) << 4);
                const uint32_t sw = (row << 7) + (col ^ ((row & 7) << 4));
                LDSM4(bh[nq][0], bh[nq][1], bh[nq][2], bh[nq][3], Bb + sw);
                LDSM4(bl[nq][0], bl[nq][1], bl[nq][2], bl[nq][3], Bb + BTSZ + sw);
            }
            #pragma unroll
            for (int mb = 0; mb < 4; ++mb)
                #pragma unroll
                for (int n = 0; n < 8; ++n) {
                    const int q0 = (n & 1) * 2;
                    MMA16816(acc[mb][n], ah[mb], bh[n >> 1][q0], bh[n >> 1][q0 + 1]);
                    MMA16816(acc[mb][n], ah[mb], bl[n >> 1][q0], bl[n >> 1][q0 + 1]);
                    MMA16816(acc[mb][n], al[mb], bh[n >> 1][q0], bh[n >> 1][q0 + 1]);
                }
        }
        __syncthreads();
    }

    const int rbase = m0 + mwarp + (lane >> 2);
    const int cbase = n0 + nwarp + (lane & 3) * 2;
    #pragma unroll
    for (int mb = 0; mb < 4; ++mb) {
        #pragma unroll
        for (int n = 0; n < 8; ++n) {
            const int gc = cbase + n * 8;
            const float bx = bias[gc];
            const float by = bias[gc + 1];
            const int r = rbase + mb * 16;
            float2 v0 = { acc[mb][n][0] + bx, acc[mb][n][1] + by };
            float2 v1 = { acc[mb][n][2] + bx, acc[mb][n][3] + by };
            *reinterpret_cast<float2*>(&C[(size_t)r * (3 * CC) + gc])       = v0;
            *reinterpret_cast<float2*>(&C[(size_t)(r + 8) * (3 * CC) + gc]) = v1;
        }
    }
}

// ===========================================================================
// wmma2_hw (128x128 CTA): 3-product fp16 split GEMM for hw.
// ===========================================================================
__global__ __launch_bounds__(256)
void wmma2_hw(const __half* __restrict__ a_hi, const __half* __restrict__ a_lo,
              const __half* __restrict__ b_hi, const __half* __restrict__ b_lo,
              __half* __restrict__ Chi, __half* __restrict__ Clo,
              int K, int lda, int ldb, int ldc)
{
    constexpr uint32_t TSZ = 16384;
    constexpr uint32_t STG = 4 * TSZ;
    extern __shared__ __align__(128) char smem[];
    const uint32_t sbase = smem_u32(smem);

    const int t     = threadIdx.x;
    const int lane  = t & 31;
    const int warp  = t >> 5;
    const int mwarp = (warp >> 1) * 32;
    const int nwarp = (warp & 1) * 64;
    const int m0 = blockIdx.y * 128;
    const int n0 = blockIdx.x * 128;

    const __half* Ah = a_hi + (size_t)m0 * lda;
    const __half* Al = a_lo + (size_t)m0 * lda;
    const __half* Bh = b_hi + (size_t)n0 * ldb;
    const __half* Bl = b_lo + (size_t)n0 * ldb;

    const int NC = K >> 6;

    float acc[2][8][4];
    #pragma unroll
    for (int i = 0; i < 2; i++)
        #pragma unroll
        for (int j = 0; j < 8; j++)
            #pragma unroll
            for (int q = 0; q < 4; q++)
                acc[i][j][q] = 0.0f;

    auto load_stage = [&](int kc, uint32_t sb) {
        cp_tile<128>(Ah, lda, sb, t, kc);
        cp_tile<128>(Al, lda, sb + TSZ, t, kc);
        cp_tile<128>(Bh, ldb, sb + 2 * TSZ, t, kc);
        cp_tile<128>(Bl, ldb, sb + 3 * TSZ, t, kc);
        CP_COMMIT();
    };

    load_stage(0, sbase);

    for (int c = 0; c < NC; ++c) {
        const int buf = c & 1;
        if (c + 1 < NC) {
            load_stage(c + 1, sbase + ((c + 1) & 1) * STG);
            CP_WAIT(1);
        } else {
            CP_WAIT(0);
        }
        __syncthreads();

        const uint32_t S = sbase + buf * STG;

        #pragma unroll
        for (int ks = 0; ks < 4; ++ks) {
            uint32_t ah[2][4], al[2][4];
            #pragma unroll
            for (int mb = 0; mb < 2; ++mb) {
                const int row = mwarp + mb * 16 + (lane & 15);
                const int col = ks * 32 + ((lane >> 4) << 4);
                const uint32_t sw = (row << 7) + (col ^ ((row & 7) << 4));
                LDSM4(ah[mb][0], ah[mb][1], ah[mb][2], ah[mb][3], S + sw);
                LDSM4(al[mb][0], al[mb][1], al[mb][2], al[mb][3], S + TSZ + sw);
            }
            uint32_t bh[4][4], bl[4][4];
            #pragma unroll
            for (int nq = 0; nq < 4; ++nq) {
                const int row = nwarp + nq * 16 + ((lane >> 4) << 3) + (lane & 7);
                const int col = ks * 32 + (((lane >> 3) & 1) << 4);
                const uint32_t sw = (row << 7) + (col ^ ((row & 7) << 4));
                LDSM4(bh[nq][0], bh[nq][1], bh[nq][2], bh[nq][3], S + 2 * TSZ + sw);
                LDSM4(bl[nq][0], bl[nq][1], bl[nq][2], bl[nq][3], S + 3 * TSZ + sw);
            }
            #pragma unroll
            for (int mb = 0; mb < 2; ++mb)
                #pragma unroll
                for (int n = 0; n < 8; ++n) {
                    const int q0 = (n & 1) * 2;
                    MMA16816(acc[mb][n], ah[mb], bh[n >> 1][q0], bh[n >> 1][q0 + 1]);
                    MMA16816(acc[mb][n], ah[mb], bl[n >> 1][q0], bl[n >> 1][q0 + 1]);
                    MMA16816(acc[mb][n], al[mb], bh[n >> 1][q0], bh[n >> 1][q0 + 1]);
                }
        }
        __syncthreads();
    }

    const int rbase = m0 + mwarp + (lane >> 2);
    const int cbase = n0 + nwarp + (lane & 3) * 2;
    #pragma unroll
    for (int mb = 0; mb < 2; ++mb) {
        #pragma unroll
        for (int n = 0; n < 8; ++n) {
            const int gc = cbase + n * 8;
            const int r  = rbase + mb * 16;
            #pragma unroll
            for (int hf = 0; hf < 2; ++hf) {
                const float v0 = acc[mb][n][hf * 2 + 0];
                const float v1 = acc[mb][n][hf * 2 + 1];
                const __half h0 = __float2half_rn(v0);
                const __half h1 = __float2half_rn(v1);
                __half2 ph; ph.x = h0; ph.y = h1;
                __half2 pl;
                pl.x = __float2half_rn(v0 - __half2float(h0));
                pl.y = __float2half_rn(v1 - __half2float(h1));
                const size_t off = (size_t)(r + hf * 8) * ldc + gc;
                *reinterpret_cast<__half2*>(&Chi[off]) = ph;
                *reinterpret_cast<__half2*>(&Clo[off]) = pl;
            }
        }
    }
}

// ===========================================================================
// prep_all: heterogeneous fusion of all prep work (one launch).
//  [0, 8192):          adj transpose 64x64 tiles (fp32 -> fp16, exact)
//  [8192, 8256):       wT_split (64 CTAs of 32x32 tiles)
//  [8256, 9792):       gate-weight splits (w_ih then w_hh, 768 each)
//  [9792, 17984):      x split (vectorized, 2 elems/thread)
// ===========================================================================
#define PREP_ADJ   8192
#define PREP_WT    (PREP_ADJ + 64)
#define PREP_GW    (PREP_WT + 1536)
#define PREP_TOTAL (PREP_GW + 8192)

__global__ __launch_bounds__(256)
void prep_all(const float* __restrict__ adj, __half* __restrict__ adjT,
              const float* __restrict__ W,
              __half* __restrict__ wThi, __half* __restrict__ wTlo,
              const float* __restrict__ w_ih, const float* __restrict__ w_hh,
              __half* __restrict__ ih_hi, __half* __restrict__ ih_lo,
              __half* __restrict__ hh_hi, __half* __restrict__ hh_lo,
              const float* __restrict__ x,
              __half* __restrict__ xhi, __half* __restrict__ xlo)
{
    __shared__ float tile[64][65];
    const int bid = blockIdx.x;
    const int t   = threadIdx.x;

    if (bid < PREP_ADJ) {
        // ---- adj transpose: 64x64 tile ----
        const int b   = bid >> 8;          // 256 tiles per batch
        const int rem = bid & 255;
        const int j0  = (rem & 15) * 64;
        const int n0  = (rem >> 4) * 64;
        const float* src = adj + (size_t)b * NN * NN;
        __half* dst = adjT + (size_t)b * NN * NN;
        #pragma unroll
        for (int k = 0; k < 4; ++k) {
            const int u  = t + k * 256;        // 0..1023
            const int r  = u >> 4;             // j row 0..63
            const int c4 = u & 15;             // float4 col
            const float4 v = *reinterpret_cast<const float4*>(
                &src[(size_t)(j0 + r) * NN + n0 + c4 * 4]);
            tile[r][c4 * 4 + 0] = v.x;
            tile[r][c4 * 4 + 1] = v.y;
            tile[r][c4 * 4 + 2] = v.z;
            tile[r][c4 * 4 + 3] = v.w;
        }
        __syncthreads();
        #pragma unroll
        for (int k = 0; k < 4; ++k) {
            const int u  = t + k * 256;
            const int rn = u >> 4;             // n row 0..63
            const int c4 = u & 15;             // group of 4 j
            __half2 p0, p1;
            p0.x = __float2half_rn(tile[c4 * 4 + 0][rn]);
            p0.y = __float2half_rn(tile[c4 * 4 + 1][rn]);
            p1.x = __float2half_rn(tile[c4 * 4 + 2][rn]);
            p1.y = __float2half_rn(tile[c4 * 4 + 3][rn]);
            __half* d = &dst[(size_t)(n0 + rn) * NN + j0 + c4 * 4];
            *reinterpret_cast<__half2*>(d)     = p0;
            *reinterpret_cast<__half2*>(d + 2) = p1;
        }
    } else if (bid < PREP_WT) {
        // ---- wT_split: weight[l] [C][C] -> WT hi/lo [l][d][c], 32x32 tile ----
        const int id  = bid - PREP_ADJ;        // 0..63
        const int l   = id >> 4;
        const int sub = id & 15;
        const int c0  = (sub & 3) * 32;
        const int d0  = (sub >> 2) * 32;
        const float* src = W + (size_t)l * CC * CC;
        const size_t ob = (size_t)l * CC * CC;
        const int tx = t & 31, ty = t >> 5;
        float (*tl)[65] = tile;
        #pragma unroll
        for (int r = ty; r < 32; r += 8)
            tl[r][tx] = src[(size_t)(c0 + r) * CC + d0 + tx];
        __syncthreads();
        #pragma unroll
        for (int r = ty; r < 32; r += 8) {
            const float v = tl[tx][r];
            const __half h = __float2half_rn(v);
            wThi[ob + (size_t)(d0 + r) * CC + c0 + tx] = h;
            wTlo[ob + (size_t)(d0 + r) * CC + c0 + tx] =
                __float2half_rn(v - __half2float(h));
        }
    } else if (bid < PREP_GW) {
        // ---- gate weight splits ----
        const int id = bid - PREP_WT;          // 0..1535
        const int half = id >= 768;
        const int i = (id - half * 768) * 256 + t;
        const float* src = half ? w_hh : w_ih;
        __half* dhi = half ? hh_hi : ih_hi;
        __half* dlo = half ? hh_lo : ih_lo;
        const float v = src[i];
        const __half h = __float2half_rn(v);
        dhi[i] = h;
        dlo[i] = __float2half_rn(v - __half2float(h));
    } else {
        // ---- x split, 2 elems/thread ----
        const int u = (bid - PREP_GW) * 256 + t;    // < HSZ/2
        const float2 v = *reinterpret_cast<const float2*>(&x[(size_t)u * 2]);
        const __half h0 = __float2half_rn(v.x);
        const __half h1 = __float2half_rn(v.y);
        __half2 ph; ph.x = h0; ph.y = h1;
        __half2 pl;
        pl.x = __float2half_rn(v.x - __half2float(h0));
        pl.y = __float2half_rn(v.y - __half2float(h1));
        *reinterpret_cast<__half2*>(&xhi[(size_t)u * 2]) = ph;
        *reinterpret_cast<__half2*>(&xlo[(size_t)u * 2]) = pl;
    }
}

// ===========================================================================
// Fused GRU elementwise (vectorized: 2 channels per thread).
// ===========================================================================
__global__ __launch_bounds__(256)
void gru_elem4(const float* __restrict__ gx, const float* __restrict__ gh,
               const __half* __restrict__ hhi_in, const __half* __restrict__ hlo_in,
               __half* __restrict__ hhi_out, __half* __restrict__ hlo_out,
               float* __restrict__ outF,
               const float* __restrict__ mask, int isLast)
{
    const int u  = blockIdx.x * blockDim.x + threadIdx.x;   // < ROWS*CC/2
    const int r  = u >> 6;             // row
    const int c0 = (u & 63) * 2;       // even channel
    const size_t idx = (size_t)r * CC + c0;
    const size_t gb  = (size_t)r * (3 * CC);

    const float2 xr = *reinterpret_cast<const float2*>(&gx[gb + c0]);
    const float2 xz = *reinterpret_cast<const float2*>(&gx[gb + CC + c0]);
    const float2 xn = *reinterpret_cast<const float2*>(&gx[gb + 2 * CC + c0]);
    const float2 hr = *reinterpret_cast<const float2*>(&gh[gb + c0]);
    const float2 hz = *reinterpret_cast<const float2*>(&gh[gb + CC + c0]);
    const float2 hn = *reinterpret_cast<const float2*>(&gh[gb + 2 * CC + c0]);
    const __half2 hh = *reinterpret_cast<const __half2*>(&hhi_in[idx]);
    const __half2 hl = *reinterpret_cast<const __half2*>(&hlo_in[idx]);
    const float h0 = __half2float(hh.x) + __half2float(hl.x);
    const float h1 = __half2float(hh.y) + __half2float(hl.y);

    const float rg0 = 1.0f / (1.0f + __expf(-(xr.x + hr.x)));
    const float rg1 = 1.0f / (1.0f + __expf(-(xr.y + hr.y)));
    const float zg0 = 1.0f / (1.0f + __expf(-(xz.x + hz.x)));
    const float zg1 = 1.0f / (1.0f + __expf(-(xz.y + hz.y)));
    const float ng0 = tanhf(xn.x + rg0 * hn.x);
    const float ng1 = tanhf(xn.y + rg1 * hn.y);
    const float hnew0 = (1.0f - zg0) * ng0 + zg0 * h0;
    const float hnew1 = (1.0f - zg1) * ng1 + zg1 * h1;

    if (isLast) {
        const float mk = mask[r];
        float2 o = { hnew0 * mk, hnew1 * mk };
        *reinterpret_cast<float2*>(&outF[idx]) = o;
    } else {
        const __half H0 = __float2half_rn(hnew0);
        const __half H1 = __float2half_rn(hnew1);
        __half2 ph; ph.x = H0; ph.y = H1;
        __half2 pl;
        pl.x = __float2half_rn(hnew0 - __half2float(H0));
        pl.y = __float2half_rn(hnew1 - __half2float(H1));
        *reinterpret_cast<__half2*>(&hhi_out[idx]) = ph;
        *reinterpret_cast<__half2*>(&hlo_out[idx]) = pl;
    }
}

// ===========================================================================
#define SMEM_BIG   (3 * (32768 + 2 * 16384))         // 192 KB
#define SMEM_HW    (2 * 4 * 16384)                   // 128 KB

extern "C" void kernel_launch(void* const* d_in, const int* in_sizes, int n_in,
                              void* d_out, int out_size)
{
    const float* x      = (const float*)d_in[0];
    const float* adj    = (const float*)d_in[1];
    const float* mask   = (const float*)d_in[2];
    const float* weight = (const float*)d_in[3];
    const float* w_ih   = (const float*)d_in[4];
    const float* w_hh   = (const float*)d_in[5];
    const float* b_ih   = (const float*)d_in[6];
    const float* b_hh   = (const float*)d_in[7];
    float* out = (float*)d_out;

    float *p_gx, *p_gh;
    __half *p_adjT, *p_hwhi, *p_hwlo, *p_mhi, *p_mlo;
    __half *p_hAhi, *p_hAlo, *p_hBhi, *p_hBlo;
    __half *p_wThi, *p_wTlo, *p_wihhi, *p_wihlo, *p_whhhi, *p_whhlo;
    cudaGetSymbolAddress((void**)&p_gx, g_gx);
    cudaGetSymbolAddress((void**)&p_gh, g_gh);
    cudaGetSymbolAddress((void**)&p_adjT, g_adjT);
    cudaGetSymbolAddress((void**)&p_hwhi, g_hwT_hi);
    cudaGetSymbolAddress((void**)&p_hwlo, g_hwT_lo);
    cudaGetSymbolAddress((void**)&p_mhi, g_mA_hi);
    cudaGetSymbolAddress((void**)&p_mlo, g_mA_lo);
    cudaGetSymbolAddress((void**)&p_hAhi, g_hA_hi);
    cudaGetSymbolAddress((void**)&p_hAlo, g_hA_lo);
    cudaGetSymbolAddress((void**)&p_hBhi, g_hB_hi);
    cudaGetSymbolAddress((void**)&p_hBlo, g_hB_lo);
    cudaGetSymbolAddress((void**)&p_wThi, g_wT_hi);
    cudaGetSymbolAddress((void**)&p_wTlo, g_wT_lo);
    cudaGetSymbolAddress((void**)&p_wihhi, g_wih_hi);
    cudaGetSymbolAddress((void**)&p_wihlo, g_wih_lo);
    cudaGetSymbolAddress((void**)&p_whhhi, g_whh_hi);
    cudaGetSymbolAddress((void**)&p_whhlo, g_whh_lo);

    cudaFuncSetAttribute(fused_adj_gh, cudaFuncAttributeMaxDynamicSharedMemorySize, SMEM_BIG);
    cudaFuncSetAttribute(gate_mma,     cudaFuncAttributeMaxDynamicSharedMemorySize, SMEM_BIG);
    cudaFuncSetAttribute(wmma2_hw,     cudaFuncAttributeMaxDynamicSharedMemorySize, SMEM_HW);

    // ---- once per call: single heterogeneous prep launch ----
    prep_all<<<PREP_TOTAL, 256>>>(
        adj, p_adjT, weight, p_wThi, p_wTlo,
        w_ih, w_hh, p_wihhi, p_wihlo, p_whhhi, p_whhlo,
        x, p_hAhi, p_hAlo);

    __half* hs_hi[2] = { p_hAhi, p_hBhi };
    __half* hs_lo[2] = { p_hAlo, p_hBlo };

    for (int l = 0; l < LL; l++) {
        __half* chi = hs_hi[l & 1];
        __half* clo = hs_lo[l & 1];
        __half* nhi = hs_hi[(l + 1) & 1];
        __half* nlo = hs_lo[(l + 1) & 1];
        const long loffW = (long)l * CC * CC;
        const long loffG = (long)l * 3 * CC * CC;

        // 1) hwT[d][b*N+j] = sum_c WT[d][c] * h[j][c]   (3-product)
        wmma2_hw<<<dim3(ROWS / 128, 1, 1), 256, SMEM_HW>>>(
            p_wThi + loffW, p_wTlo + loffW, chi, clo,
            p_hwhi, p_hwlo, CC, CC, CC, ROWS);

        // 2) fused: m = adjT @ (hw_hi+hw_lo)  AND  gh = h @ w_hh^T + b_hh
        fused_adj_gh<<<512, 256, SMEM_BIG>>>(
            p_adjT, p_hwhi, p_hwlo, p_mhi, p_mlo,
            chi, clo, p_whhhi + loffG, p_whhlo + loffG,
            p_gh, b_hh + (long)l * 3 * CC);

        // 3) gx = m @ w_ih^T + b_ih
        gate_mma<<<dim3(3, ROWS / 256), 256, SMEM_BIG>>>(
            p_mhi, p_mlo, p_wihhi + loffG, p_wihlo + loffG,
            p_gx, b_ih + (long)l * 3 * CC);

        // 4) GRU elementwise (vectorized, 2 ch/thread)
        gru_elem4<<<(ROWS * CC / 2) / 256, 256>>>(
            p_gx, p_gh, chi, clo, nhi, nlo, out, mask, (l == LL - 1) ? 1 : 0);
    }
}